// round 12
// baseline (speedup 1.0000x reference)
#include <cuda_runtime.h>
#include <cuda_bf16.h>
#include <math.h>
#include <stdint.h>

#define Bb   4
#define Tt   1024
#define Dd   1024
#define Hh   16
#define HSs  64
#define Ll   4
#define FFf  4096
#define Vv   32000
#define BT   (Bb*Tt)
#define EPSf 1e-5f

typedef __nv_bfloat16 bf16;

__device__ float g_x[BT*Dd];
__device__ float g_logits[(size_t)BT*Vv];
__device__ float g_rownll[BT];
__device__ __align__(16) bf16 g_hH[BT*Dd],  g_hL[BT*Dd];
__device__ __align__(16) bf16 g_qH[BT*Dd],  g_qL[BT*Dd];
__device__ __align__(16) bf16 g_kH[BT*Dd],  g_kL[BT*Dd];
__device__ __align__(16) bf16 g_vH[BT*Dd],  g_vL[BT*Dd];
__device__ __align__(16) bf16 g_oH[BT*Dd],  g_oL[BT*Dd];
__device__ __align__(16) bf16 g_ffH[(size_t)BT*FFf], g_ffL[(size_t)BT*FFf];
__device__ __align__(16) bf16 g_wH[(size_t)Bb*Hh*Tt*Tt], g_wL[(size_t)Bb*Hh*Tt*Tt];
__device__ __align__(16) bf16 g_wqT_h[Ll*Hh*HSs*Dd], g_wqT_l[Ll*Hh*HSs*Dd];
__device__ __align__(16) bf16 g_wkT_h[Ll*Hh*HSs*Dd], g_wkT_l[Ll*Hh*HSs*Dd];
__device__ __align__(16) bf16 g_wvT_h[Ll*Hh*HSs*Dd], g_wvT_l[Ll*Hh*HSs*Dd];
__device__ __align__(16) bf16 g_wpT_h[(size_t)Ll*Dd*Dd], g_wpT_l[(size_t)Ll*Dd*Dd];
__device__ __align__(16) bf16 g_w1T_h[(size_t)Ll*FFf*Dd], g_w1T_l[(size_t)Ll*FFf*Dd];
__device__ __align__(16) bf16 g_w2T_h[(size_t)Ll*Dd*FFf], g_w2T_l[(size_t)Ll*Dd*FFf];
__device__ __align__(16) bf16 g_wlmT_h[(size_t)Vv*Dd];

__device__ __forceinline__ uint32_t smem_u32(const void* p) {
    uint32_t a;
    asm("{ .reg .u64 t; cvta.to.shared.u64 t, %1; cvt.u32.u64 %0, t; }" : "=r"(a) : "l"(p));
    return a;
}
__device__ __forceinline__ void ldsm4(uint32_t& r0, uint32_t& r1, uint32_t& r2,
                                      uint32_t& r3, uint32_t addr) {
    asm volatile("ldmatrix.sync.aligned.m8n8.x4.shared.b16 {%0,%1,%2,%3}, [%4];"
                 : "=r"(r0), "=r"(r1), "=r"(r2), "=r"(r3) : "r"(addr));
}
__device__ __forceinline__ void mma16816(float* c, const uint32_t* a, const uint32_t* b) {
    asm volatile(
        "mma.sync.aligned.m16n8k16.row.col.f32.bf16.bf16.f32 "
        "{%0,%1,%2,%3}, {%4,%5,%6,%7}, {%8,%9}, {%0,%1,%2,%3};"
        : "+f"(c[0]), "+f"(c[1]), "+f"(c[2]), "+f"(c[3])
        : "r"(a[0]), "r"(a[1]), "r"(a[2]), "r"(a[3]), "r"(b[0]), "r"(b[1]));
}
__device__ __forceinline__ void cpa16(uint32_t s, const void* g) {
    asm volatile("cp.async.cg.shared.global [%0], [%1], 16;" :: "r"(s), "l"(g));
}
__device__ __forceinline__ void cpa_commit() {
    asm volatile("cp.async.commit_group;" ::: "memory");
}
__device__ __forceinline__ void cpa_wait0() {
    asm volatile("cp.async.wait_group 0;" ::: "memory");
}
__device__ __forceinline__ void fsplit(float v, bf16& h, bf16& l) {
    h = __float2bfloat16(v);
    l = __float2bfloat16(v - __bfloat162float(h));
}

// ---------------- fused weight transpose + split (up to 4 weights) ----------
struct WSDesc { const float* W; bf16* H; bf16* L; int R, C, nz; };

__global__ void wsplit_multi(WSDesc d0, WSDesc d1, WSDesc d2, WSDesc d3,
                             int nb0, int nb1, int nb2, int nb3) {
    __shared__ float ts[32][33];
    int id = blockIdx.x;
    WSDesc d;
    if (id < nb0) { d = d0; }
    else if (id < nb0 + nb1) { d = d1; id -= nb0; }
    else if (id < nb0 + nb1 + nb2) { d = d2; id -= nb0 + nb1; }
    else { d = d3; id -= nb0 + nb1 + nb2; }
    int nbx = d.C >> 5, nby = d.R >> 5;
    int z = id / (nbx * nby);
    int rem = id - z * nbx * nby;
    int by = rem / nbx, bx = rem - by * nbx;
    size_t mo = (size_t)z * d.R * d.C;
    int c0 = bx * 32, r0 = by * 32;
    int tx = threadIdx.x, ty = threadIdx.y;
    #pragma unroll
    for (int i = 0; i < 4; ++i) {
        int r = r0 + ty + i * 8;
        ts[ty + i * 8][tx] = d.W[mo + (size_t)r * d.C + c0 + tx];
    }
    __syncthreads();
    #pragma unroll
    for (int i = 0; i < 4; ++i) {
        int n = c0 + ty + i * 8;
        int k = r0 + tx;
        float v = ts[tx][ty + i * 8];
        bf16 h = __float2bfloat16(v);
        d.H[mo + (size_t)n * d.R + k] = h;
        if (d.L)
            d.L[mo + (size_t)n * d.R + k] = __float2bfloat16(v - __bfloat162float(h));
    }
}

// ---------------- unified bf16 hi/lo tensor-core GEMM -----------------------
// OMODE 0: fp32 +bias/resid/relu | 1: scores | 3: bf16 linear | 5: fused QKV
// NPROD 3: ah*bh + ah*bl + al*bh | NPROD 1: ah*bh only (pure bf16)
// KCAUS: truncate K to (blockIdx.x+1)*128 (attn·V; wei is causal-zero beyond)
// MAXCTA: blocks-per-SM hint (2 for BN=128, 1 for BN=256)
struct QKVP {
    const bf16 *bh0, *bl0, *bh1, *bl1, *bh2, *bl2;
    bf16 *ch0, *cl0, *ch1, *cl1, *ch2, *cl2;
};

template<int BN, int OMODE, int NPROD, bool KCAUS, int MAXCTA>
__global__ __launch_bounds__(256, MAXCTA)
void gmma_kernel(const bf16* __restrict__ Ah, const bf16* __restrict__ Al,
                 const bf16* __restrict__ Bhp, const bf16* __restrict__ Blp,
                 float* __restrict__ C, bf16* __restrict__ Chp, bf16* __restrict__ Clp,
                 const float* __restrict__ bias, const float* __restrict__ resid,
                 int relu, int K, int lda, int ldb, int ldc,
                 size_t aZh, size_t aZl, size_t bZh, size_t bZl,
                 size_t cZh, size_t cZl, QKVP qp) {
    constexpr int STR = 80;
    constexpr int ALO = 128 * STR;
    constexpr int AROWS = (NPROD >= 3) ? 256 : 128;     // A hi (+lo) rows
    constexpr int BROWS = BN * ((NPROD == 3) ? 2 : 1);  // B hi (+lo) rows
    constexpr int BHO = AROWS * STR;
    constexpr int BLO = BHO + BN * STR;
    constexpr int SSZ = (AROWS + BROWS) * STR;
    constexpr int NT8 = BN / 32;
    constexpr int NB16 = NT8 / 2;
    constexpr int BSEG = BN * 4 / 256;
    extern __shared__ __align__(16) unsigned char smem[];

    int m0 = blockIdx.x * 128, n0 = blockIdx.y * BN;
    if (OMODE == 1 && n0 > m0) return;
    int z = blockIdx.z;
    const bf16 *Bh, *Bl = nullptr;
    bf16 *Ch = nullptr, *Cl = nullptr;
    if (OMODE == 5) {
        if (z == 0)      { Bh = qp.bh0; Bl = qp.bl0; Ch = qp.ch0; Cl = qp.cl0; }
        else if (z == 1) { Bh = qp.bh1; Bl = qp.bl1; Ch = qp.ch1; Cl = qp.cl1; }
        else             { Bh = qp.bh2; Bl = qp.bl2; Ch = qp.ch2; Cl = qp.cl2; }
    } else {
        Ah += (size_t)(z >> 4) * aZh + (size_t)(z & 15) * aZl;
        Al += (size_t)(z >> 4) * aZh + (size_t)(z & 15) * aZl;
        Bh = Bhp + (size_t)(z >> 4) * bZh + (size_t)(z & 15) * bZl;
        if (NPROD == 3) Bl = Blp + (size_t)(z >> 4) * bZh + (size_t)(z & 15) * bZl;
        if (OMODE == 0 || OMODE == 1)
            C += (size_t)(z >> 4) * cZh + (size_t)(z & 15) * cZl;
        else {
            Ch = Chp + (size_t)(z >> 4) * cZh + (size_t)(z & 15) * cZl;
            Cl = Clp + (size_t)(z >> 4) * cZh + (size_t)(z & 15) * cZl;
        }
    }

    int tid = threadIdx.x, lane = tid & 31, wid = tid >> 5;
    int wm = (wid & 1) * 64;
    int wn = (wid >> 1) * (BN / 4);

    float acc[4][NT8][4];
    #pragma unroll
    for (int i = 0; i < 4; ++i)
        #pragma unroll
        for (int j = 0; j < NT8; ++j)
            #pragma unroll
            for (int q = 0; q < 4; ++q) acc[i][j][q] = 0.f;

    uint32_t sbase = smem_u32(smem);
    int NC = KCAUS ? (blockIdx.x + 1) * 4 : (K / 32);

    auto load_stage = [&](int c) {
        uint32_t stg = sbase + (uint32_t)(c & 1) * SSZ;
        int kc = c * 32;
        #pragma unroll
        for (int i = 0; i < 2; ++i) {
            int slot = i * 256 + tid, r = slot >> 2, sg = slot & 3;
            uint32_t so = r * STR + sg * 16;
            size_t go = (size_t)(m0 + r) * lda + kc + sg * 8;
            cpa16(stg + so, Ah + go);
            if (NPROD >= 3) cpa16(stg + ALO + so, Al + go);
        }
        #pragma unroll
        for (int i = 0; i < BSEG; ++i) {
            int slot = i * 256 + tid, r = slot >> 2, sg = slot & 3;
            uint32_t so = r * STR + sg * 16;
            size_t go = (size_t)(n0 + r) * ldb + kc + sg * 8;
            cpa16(stg + BHO + so, Bh + go);
            if (NPROD == 3) cpa16(stg + BLO + so, Bl + go);
        }
        cpa_commit();
    };

    load_stage(0);
    uint32_t aAddr0 = sbase + (uint32_t)(wm + (lane & 15)) * STR + (lane >> 4) * 16;
    uint32_t bAddr0 = sbase + BHO + (uint32_t)(wn + (lane & 15)) * STR + (lane >> 4) * 16;

    for (int c = 0; c < NC; ++c) {
        cpa_wait0();
        __syncthreads();
        if (c + 1 < NC) load_stage(c + 1);
        uint32_t stg = (uint32_t)(c & 1) * SSZ;
        uint32_t aAddr = aAddr0 + stg, bAddr = bAddr0 + stg;
        #pragma unroll
        for (int ks = 0; ks < 2; ++ks) {
            uint32_t a[4][4];
            uint32_t bh[NT8][2], bl[NT8][2];
            #pragma unroll
            for (int g = 0; g < NB16; ++g) {
                uint32_t base = bAddr + g * 16 * STR + ks * 32;
                uint32_t r0, r1, r2, r3;
                ldsm4(r0, r1, r2, r3, base);
                bh[2*g][0] = r0; bh[2*g][1] = r2;
                bh[2*g+1][0] = r1; bh[2*g+1][1] = r3;
                if (NPROD == 3) {
                    ldsm4(r0, r1, r2, r3, base + BN * STR);
                    bl[2*g][0] = r0; bl[2*g][1] = r2;
                    bl[2*g+1][0] = r1; bl[2*g+1][1] = r3;
                }
            }
            #pragma unroll
            for (int mt = 0; mt < 4; ++mt) {
                uint32_t base = aAddr + mt * 16 * STR + ks * 32;
                ldsm4(a[mt][0], a[mt][1], a[mt][2], a[mt][3], base);
            }
            #pragma unroll
            for (int mt = 0; mt < 4; ++mt)
                #pragma unroll
                for (int n8 = 0; n8 < NT8; ++n8) {
                    mma16816(acc[mt][n8], a[mt], bh[n8]);
                    if (NPROD == 3) mma16816(acc[mt][n8], a[mt], bl[n8]);
                }
            if (NPROD >= 3) {
                #pragma unroll
                for (int mt = 0; mt < 4; ++mt) {
                    uint32_t base = aAddr + ALO + mt * 16 * STR + ks * 32;
                    ldsm4(a[mt][0], a[mt][1], a[mt][2], a[mt][3], base);
                }
                #pragma unroll
                for (int mt = 0; mt < 4; ++mt)
                    #pragma unroll
                    for (int n8 = 0; n8 < NT8; ++n8)
                        mma16816(acc[mt][n8], a[mt], bh[n8]);
            }
        }
    }

    int gid = lane >> 2, tig = lane & 3;
    #pragma unroll
    for (int mt = 0; mt < 4; ++mt) {
        #pragma unroll
        for (int n8 = 0; n8 < NT8; ++n8) {
            int colb = n0 + wn + n8 * 8 + tig * 2;
            #pragma unroll
            for (int h2 = 0; h2 < 2; ++h2) {
                int m = m0 + wm + mt * 16 + gid + h2 * 8;
                #pragma unroll
                for (int cc = 0; cc < 2; ++cc) {
                    int n = colb + cc;
                    float v = acc[mt][n8][h2 * 2 + cc];
                    if (OMODE == 0) {
                        if (bias) v += bias[n];
                        if (resid) v += resid[(size_t)m * ldc + n];
                        if (relu) v = fmaxf(v, 0.f);
                        C[(size_t)m * ldc + n] = v;
                    } else if (OMODE == 1) {
                        C[(size_t)m * ldc + n] = v * 0.125f;
                    } else if (OMODE == 3) {
                        if (bias) v += bias[n];
                        if (relu) v = fmaxf(v, 0.f);
                        bf16 h, l; fsplit(v, h, l);
                        Ch[(size_t)m * ldc + n] = h;
                        Cl[(size_t)m * ldc + n] = l;
                    } else {  // OMODE 5
                        int b = m >> 10, t = m & 1023;
                        bf16 h, l; fsplit(v, h, l);
                        if (z < 2) {   // q, k: [bh][t][64]
                            size_t o = (size_t)(((b * 16 + (n >> 6)) << 10) + t) * 64 + (n & 63);
                            Ch[o] = h; Cl[o] = l;
                        } else {       // v: [bh][s][t]
                            size_t o = ((size_t)((b * 16 + (n >> 6)) * 64 + (n & 63)) << 10) + t;
                            Ch[o] = h; Cl[o] = l;
                        }
                    }
                }
            }
        }
    }
}

__global__ void embed_kernel(const int* __restrict__ idx,
                             const float* __restrict__ tok,
                             const float* __restrict__ pos) {
    size_t i = (size_t)blockIdx.x * 256 + threadIdx.x;
    int d  = (int)(i & (Dd - 1));
    int bt = (int)(i >> 10);
    int t  = bt & (Tt - 1);
    g_x[i] = tok[(size_t)idx[bt] * Dd + d] + pos[(size_t)t * Dd + d];
}

__global__ void ln_kernel(const float* __restrict__ x,
                          const float* __restrict__ g,
                          const float* __restrict__ b,
                          bf16* __restrict__ oh, bf16* __restrict__ ol) {
    __shared__ float s1[8], s2[8];
    int row = blockIdx.x;
    int tid = threadIdx.x, lane = tid & 31, wrp = tid >> 5;
    const float4* xr = (const float4*)(x + (size_t)row * Dd);
    float4 v = xr[tid];
    float a  = v.x + v.y + v.z + v.w;
    float a2 = v.x*v.x + v.y*v.y + v.z*v.z + v.w*v.w;
    #pragma unroll
    for (int o = 16; o > 0; o >>= 1) {
        a  += __shfl_xor_sync(~0u, a, o);
        a2 += __shfl_xor_sync(~0u, a2, o);
    }
    if (lane == 0) { s1[wrp] = a; s2[wrp] = a2; }
    __syncthreads();
    a = 0.f; a2 = 0.f;
    #pragma unroll
    for (int w = 0; w < 8; ++w) { a += s1[w]; a2 += s2[w]; }
    float mean = a * (1.f / Dd);
    float var  = a2 * (1.f / Dd) - mean * mean;
    float rstd = rsqrtf(var + EPSf);
    float4 gv = ((const float4*)g)[tid];
    float4 bv = ((const float4*)b)[tid];
    float r0 = (v.x - mean) * rstd * gv.x + bv.x;
    float r1 = (v.y - mean) * rstd * gv.y + bv.y;
    float r2 = (v.z - mean) * rstd * gv.z + bv.z;
    float r3 = (v.w - mean) * rstd * gv.w + bv.w;
    bf16 h0,l0,h1,l1,h2,l2,h3,l3;
    fsplit(r0,h0,l0); fsplit(r1,h1,l1); fsplit(r2,h2,l2); fsplit(r3,h3,l3);
    __nv_bfloat162 hv0{h0,h1}, hv1{h2,h3}, lv0{l0,l1}, lv1{l2,l3};
    uint2 hp, lp;
    hp.x = *(uint32_t*)&hv0; hp.y = *(uint32_t*)&hv1;
    lp.x = *(uint32_t*)&lv0; lp.y = *(uint32_t*)&lv1;
    ((uint2*)(oh + (size_t)row * Dd))[tid] = hp;
    ((uint2*)(ol + (size_t)row * Dd))[tid] = lp;
}

__global__ void softmax_kernel(float* __restrict__ attnL,
                               bf16* __restrict__ WH, bf16* __restrict__ WL) {
    __shared__ float sm[8];
    int rgl = blockIdx.x;
    int bh = rgl >> 10, t = rgl & (Tt - 1);
    size_t off = ((size_t)bh << 20) + ((size_t)t << 10);
    float* p = attnL + off;
    bf16* wh = WH + off;
    bf16* wl = WL + off;
    int tid = threadIdx.x, lane = tid & 31, wrp = tid >> 5;
    float v[4];
    float mx = -3.4e38f;
    #pragma unroll
    for (int k = 0; k < 4; ++k) {
        int i = k * 256 + tid;
        float x = p[i];
        v[k] = (i <= t) ? x : -3.4e38f;
        mx = fmaxf(mx, v[k]);
    }
    #pragma unroll
    for (int o = 16; o > 0; o >>= 1) mx = fmaxf(mx, __shfl_xor_sync(~0u, mx, o));
    if (lane == 0) sm[wrp] = mx;
    __syncthreads();
    mx = sm[0];
    #pragma unroll
    for (int w = 1; w < 8; ++w) mx = fmaxf(mx, sm[w]);
    float e[4], s = 0.f;
    #pragma unroll
    for (int k = 0; k < 4; ++k) {
        int i = k * 256 + tid;
        e[k] = (i <= t) ? __expf(v[k] - mx) : 0.f;
        s += e[k];
    }
    #pragma unroll
    for (int o = 16; o > 0; o >>= 1) s += __shfl_xor_sync(~0u, s, o);
    __syncthreads();
    if (lane == 0) sm[wrp] = s;
    __syncthreads();
    s = 0.f;
    #pragma unroll
    for (int w = 0; w < 8; ++w) s += sm[w];
    float inv = 1.f / s;
    #pragma unroll
    for (int k = 0; k < 4; ++k) {
        int i = k * 256 + tid;
        float r = e[k] * inv;
        p[i] = r;
        bf16 h, l; fsplit(r, h, l);
        wh[i] = h; wl[i] = l;
    }
}

__global__ void loss_row_kernel(const int* __restrict__ targets) {
    __shared__ float sd[8];
    int r = blockIdx.x;
    const float4* p4 = (const float4*)(g_logits + (size_t)r * Vv);
    int tid = threadIdx.x, lane = tid & 31, wrp = tid >> 5;
    float mx = -3.4e38f;
    for (int i = tid; i < Vv / 4; i += 256) {
        float4 v = p4[i];
        mx = fmaxf(fmaxf(mx, fmaxf(v.x, v.y)), fmaxf(v.z, v.w));
    }
    #pragma unroll
    for (int o = 16; o > 0; o >>= 1) mx = fmaxf(mx, __shfl_xor_sync(~0u, mx, o));
    if (lane == 0) sd[wrp] = mx;
    __syncthreads();
    mx = sd[0];
    #pragma unroll
    for (int w = 1; w < 8; ++w) mx = fmaxf(mx, sd[w]);
    __syncthreads();
    float sum = 0.f;
    for (int i = tid; i < Vv / 4; i += 256) {
        float4 v = p4[i];
        sum += __expf(v.x - mx) + __expf(v.y - mx) + __expf(v.z - mx) + __expf(v.w - mx);
    }
    #pragma unroll
    for (int o = 16; o > 0; o >>= 1) sum += __shfl_xor_sync(~0u, sum, o);
    if (lane == 0) sd[wrp] = sum;
    __syncthreads();
    if (tid == 0) {
        float s = 0.f;
        #pragma unroll
        for (int w = 0; w < 8; ++w) s += sd[w];
        g_rownll[r] = logf(s) + mx - g_logits[(size_t)r * Vv + targets[r]];
    }
}

__global__ void loss_final_kernel(float* __restrict__ out) {
    __shared__ float sd[256];
    int tid = threadIdx.x;
    float s = 0.f;
    for (int i = tid; i < BT; i += 256) s += g_rownll[i];
    sd[tid] = s; __syncthreads();
    for (int st = 128; st > 0; st >>= 1) {
        if (tid < st) sd[tid] += sd[tid + st];
        __syncthreads();
    }
    if (tid == 0) out[0] = sd[0] * (1.f / BT);
}

#define SM128_3 (2 * ((256 + 256) * 80))   // 81920
#define SM64_3  (2 * ((256 + 128) * 80))   // 61440
#define SM256_3 (2 * ((256 + 512) * 80))   // 122880
#define SM256_1 (2 * ((128 + 256) * 80))   // 61440

extern "C" void kernel_launch(void* const* d_in, const int* in_sizes, int n_in,
                              void* d_out, int out_size) {
    (void)in_sizes; (void)n_in; (void)out_size;
    const int*   idx     = (const int*)d_in[0];
    const int*   targets = (const int*)d_in[1];
    const float* tok     = (const float*)d_in[2];
    const float* pos     = (const float*)d_in[3];
    const float* ln1_g   = (const float*)d_in[4];
    const float* ln1_b   = (const float*)d_in[5];
    const float* Wq      = (const float*)d_in[6];
    const float* Wk      = (const float*)d_in[7];
    const float* Wv      = (const float*)d_in[8];
    const float* Wp      = (const float*)d_in[9];
    const float* bp      = (const float*)d_in[10];
    const float* ln2_g   = (const float*)d_in[11];
    const float* ln2_b   = (const float*)d_in[12];
    const float* W1      = (const float*)d_in[13];
    const float* b1      = (const float*)d_in[14];
    const float* W2      = (const float*)d_in[15];
    const float* b2      = (const float*)d_in[16];
    const float* lnf_g   = (const float*)d_in[17];
    const float* lnf_b   = (const float*)d_in[18];
    const float* Wlm     = (const float*)d_in[19];
    const float* blm     = (const float*)d_in[20];

    float* out  = (float*)d_out;
    float* attn = out + 1;

    cudaFuncSetAttribute(gmma_kernel<128, 0, 3, false, 2>, cudaFuncAttributeMaxDynamicSharedMemorySize, SM128_3);
    cudaFuncSetAttribute(gmma_kernel<128, 1, 3, false, 2>, cudaFuncAttributeMaxDynamicSharedMemorySize, SM128_3);
    cudaFuncSetAttribute(gmma_kernel<128, 5, 3, false, 2>, cudaFuncAttributeMaxDynamicSharedMemorySize, SM128_3);
    cudaFuncSetAttribute(gmma_kernel<64,  3, 3, true,  2>, cudaFuncAttributeMaxDynamicSharedMemorySize, SM64_3);
    cudaFuncSetAttribute(gmma_kernel<256, 3, 3, false, 1>, cudaFuncAttributeMaxDynamicSharedMemorySize, SM256_3);
    cudaFuncSetAttribute(gmma_kernel<256, 0, 1, false, 1>, cudaFuncAttributeMaxDynamicSharedMemorySize, SM256_1);

    float *px, *plog;
    cudaGetSymbolAddress((void**)&px,   g_x);
    cudaGetSymbolAddress((void**)&plog, g_logits);
    bf16 *hH,*hL,*qH,*qL,*kH,*kL,*vH,*vL,*oH,*oL,*fH,*fL,*wH,*wL;
    cudaGetSymbolAddress((void**)&hH, g_hH); cudaGetSymbolAddress((void**)&hL, g_hL);
    cudaGetSymbolAddress((void**)&qH, g_qH); cudaGetSymbolAddress((void**)&qL, g_qL);
    cudaGetSymbolAddress((void**)&kH, g_kH); cudaGetSymbolAddress((void**)&kL, g_kL);
    cudaGetSymbolAddress((void**)&vH, g_vH); cudaGetSymbolAddress((void**)&vL, g_vL);
    cudaGetSymbolAddress((void**)&oH, g_oH); cudaGetSymbolAddress((void**)&oL, g_oL);
    cudaGetSymbolAddress((void**)&fH, g_ffH); cudaGetSymbolAddress((void**)&fL, g_ffL);
    cudaGetSymbolAddress((void**)&wH, g_wH); cudaGetSymbolAddress((void**)&wL, g_wL);
    bf16 *wqh,*wql,*wkh,*wkl,*wvh,*wvl,*wph,*wpl,*w1h,*w1l,*w2h,*w2l,*wlh;
    cudaGetSymbolAddress((void**)&wqh, g_wqT_h); cudaGetSymbolAddress((void**)&wql, g_wqT_l);
    cudaGetSymbolAddress((void**)&wkh, g_wkT_h); cudaGetSymbolAddress((void**)&wkl, g_wkT_l);
    cudaGetSymbolAddress((void**)&wvh, g_wvT_h); cudaGetSymbolAddress((void**)&wvl, g_wvT_l);
    cudaGetSymbolAddress((void**)&wph, g_wpT_h); cudaGetSymbolAddress((void**)&wpl, g_wpT_l);
    cudaGetSymbolAddress((void**)&w1h, g_w1T_h); cudaGetSymbolAddress((void**)&w1l, g_w1T_l);
    cudaGetSymbolAddress((void**)&w2h, g_w2T_h); cudaGetSymbolAddress((void**)&w2l, g_w2T_l);
    cudaGetSymbolAddress((void**)&wlh, g_wlmT_h);

    {
        WSDesc a0{Wq, wqh, wql, Dd, HSs, Ll*Hh};
        WSDesc a1{Wk, wkh, wkl, Dd, HSs, Ll*Hh};
        WSDesc a2{Wv, wvh, wvl, Dd, HSs, Ll*Hh};
        WSDesc a3{Wp, wph, wpl, Dd, Dd,  Ll};
        int nb0 = (HSs/32)*(Dd/32)*Ll*Hh, nb3 = (Dd/32)*(Dd/32)*Ll;
        wsplit_multi<<<nb0*3 + nb3, dim3(32, 8)>>>(a0, a1, a2, a3, nb0, nb0, nb0, nb3);
        WSDesc b0{W1, w1h, w1l, Dd, FFf, Ll};
        WSDesc b1{W2, w2h, w2l, FFf, Dd, Ll};
        WSDesc b2{Wlm, wlh, nullptr, Dd, Vv, 1};
        WSDesc b3{Wlm, wlh, nullptr, Dd, Vv, 0};
        int m0n = (FFf/32)*(Dd/32)*Ll, m1n = (Dd/32)*(FFf/32)*Ll, m2n = (Vv/32)*(Dd/32);
        wsplit_multi<<<m0n + m1n + m2n, dim3(32, 8)>>>(b0, b1, b2, b3, m0n, m1n, m2n, 0);
    }

    embed_kernel<<<BT * Dd / 256, 256>>>(idx, tok, pos);

    QKVP qpz{};
    const size_t WQL = (size_t)Hh * HSs * Dd;
    for (int l = 0; l < Ll; ++l) {
        float* attnL = attn + (size_t)l * Bb * Hh * Tt * Tt;

        ln_kernel<<<BT, 256>>>(px, ln1_g + (size_t)l * Dd, ln1_b + (size_t)l * Dd, hH, hL);

        QKVP qp{wqh + l * WQL, wql + l * WQL,
                wkh + l * WQL, wkl + l * WQL,
                wvh + l * WQL, wvl + l * WQL,
                qH, qL, kH, kL, vH, vL};
        gmma_kernel<128, 5, 3, false, 2><<<dim3(32, 8, 3), 256, SM128_3>>>(
            hH, hL, nullptr, nullptr, nullptr, nullptr, nullptr,
            nullptr, nullptr, 0, Dd, Dd, Dd, Dd, 0, 0, 0, 0, 0, 0, qp);

        gmma_kernel<128, 1, 3, false, 2><<<dim3(8, 8, Bb * Hh), 256, SM128_3>>>(
            qH, qL, kH, kL, attnL, nullptr, nullptr, nullptr, nullptr, 0,
            HSs, HSs, HSs, Tt,
            (size_t)16 * Tt * HSs, (size_t)Tt * HSs,
            (size_t)16 * Tt * HSs, (size_t)Tt * HSs,
            (size_t)16 * Tt * Tt, (size_t)Tt * Tt, qpz);

        softmax_kernel<<<Bb * Hh * Tt, 256>>>(attnL, wH, wL);

        gmma_kernel<64, 3, 3, true, 2><<<dim3(8, 1, Bb * Hh), 256, SM64_3>>>(
            wH, wL, vH, vL, nullptr, oH, oL, nullptr, nullptr, 0,
            Tt, Tt, Tt, Dd,
            (size_t)16 * Tt * Tt, (size_t)Tt * Tt,
            (size_t)16 * HSs * Tt, (size_t)HSs * Tt,
            (size_t)Tt * Dd, HSs, qpz);

        gmma_kernel<128, 0, 3, false, 2><<<dim3(32, 8, 1), 256, SM128_3>>>(
            oH, oL, wph + (size_t)l * Dd * Dd, wpl + (size_t)l * Dd * Dd,
            px, nullptr, nullptr, bp + (size_t)l * Dd, px, 0,
            Dd, Dd, Dd, Dd, 0, 0, 0, 0, 0, 0, qpz);

        ln_kernel<<<BT, 256>>>(px, ln2_g + (size_t)l * Dd, ln2_b + (size_t)l * Dd, hH, hL);

        // MLP1: BN=256 tiles (N=4096)
        gmma_kernel<256, 3, 3, false, 1><<<dim3(32, 16, 1), 256, SM256_3>>>(
            hH, hL, w1h + (size_t)l * Dd * FFf, w1l + (size_t)l * Dd * FFf,
            nullptr, fH, fL, b1 + (size_t)l * FFf, nullptr, 1,
            Dd, Dd, Dd, FFf, 0, 0, 0, 0, 0, 0, qpz);

        gmma_kernel<128, 0, 3, false, 2><<<dim3(32, 8, 1), 256, SM128_3>>>(
            fH, fL, w2h + (size_t)l * FFf * Dd, w2l + (size_t)l * FFf * Dd,
            px, nullptr, nullptr, b2 + (size_t)l * Dd, px, 0,
            FFf, FFf, FFf, Dd, 0, 0, 0, 0, 0, 0, qpz);
    }

    ln_kernel<<<BT, 256>>>(px, lnf_g, lnf_b, hH, hL);

    // LM head: BN=256, 1-product pure bf16 — feeds only the scalar loss
    gmma_kernel<256, 0, 1, false, 1><<<dim3(32, 125, 1), 256, SM256_1>>>(
        hH, hL, wlh, nullptr, plog, nullptr, nullptr, blm, nullptr, 0,
        Dd, Dd, Dd, Vv, 0, 0, 0, 0, 0, 0, qpz);

    loss_row_kernel<<<BT, 256>>>(targets);
    loss_final_kernel<<<1, 256>>>(out);
}

// round 13
// speedup vs baseline: 1.0856x; 1.0856x over previous
#include <cuda_runtime.h>
#include <cuda_bf16.h>
#include <math.h>
#include <stdint.h>

#define Bb   4
#define Tt   1024
#define Dd   1024
#define Hh   16
#define HSs  64
#define Ll   4
#define FFf  4096
#define Vv   32000
#define BT   (Bb*Tt)
#define NTIL 250          // head N tiles (32000/128)
#define EPSf 1e-5f

typedef __nv_bfloat16 bf16;

__device__ float g_x[BT*Dd];
__device__ float g_rownll[BT];
__device__ float g_pmax[NTIL*BT], g_psum[NTIL*BT], g_tgt[BT];
__device__ __align__(16) bf16 g_hH[BT*Dd],  g_hL[BT*Dd];
__device__ __align__(16) bf16 g_qH[BT*Dd],  g_qL[BT*Dd];
__device__ __align__(16) bf16 g_kH[BT*Dd],  g_kL[BT*Dd];
__device__ __align__(16) bf16 g_vH[BT*Dd],  g_vL[BT*Dd];
__device__ __align__(16) bf16 g_oH[BT*Dd],  g_oL[BT*Dd];
__device__ __align__(16) bf16 g_ffH[(size_t)BT*FFf], g_ffL[(size_t)BT*FFf];
__device__ __align__(16) bf16 g_wH[(size_t)Bb*Hh*Tt*Tt], g_wL[(size_t)Bb*Hh*Tt*Tt];
__device__ __align__(16) bf16 g_wqT_h[Ll*Hh*HSs*Dd], g_wqT_l[Ll*Hh*HSs*Dd];
__device__ __align__(16) bf16 g_wkT_h[Ll*Hh*HSs*Dd], g_wkT_l[Ll*Hh*HSs*Dd];
__device__ __align__(16) bf16 g_wvT_h[Ll*Hh*HSs*Dd], g_wvT_l[Ll*Hh*HSs*Dd];
__device__ __align__(16) bf16 g_wpT_h[(size_t)Ll*Dd*Dd], g_wpT_l[(size_t)Ll*Dd*Dd];
__device__ __align__(16) bf16 g_w1T_h[(size_t)Ll*FFf*Dd], g_w1T_l[(size_t)Ll*FFf*Dd];
__device__ __align__(16) bf16 g_w2T_h[(size_t)Ll*Dd*FFf], g_w2T_l[(size_t)Ll*Dd*FFf];
__device__ __align__(16) bf16 g_wlmT_h[(size_t)Vv*Dd];

__device__ __forceinline__ uint32_t smem_u32(const void* p) {
    uint32_t a;
    asm("{ .reg .u64 t; cvta.to.shared.u64 t, %1; cvt.u32.u64 %0, t; }" : "=r"(a) : "l"(p));
    return a;
}
__device__ __forceinline__ void ldsm4(uint32_t& r0, uint32_t& r1, uint32_t& r2,
                                      uint32_t& r3, uint32_t addr) {
    asm volatile("ldmatrix.sync.aligned.m8n8.x4.shared.b16 {%0,%1,%2,%3}, [%4];"
                 : "=r"(r0), "=r"(r1), "=r"(r2), "=r"(r3) : "r"(addr));
}
__device__ __forceinline__ void mma16816(float* c, const uint32_t* a, const uint32_t* b) {
    asm volatile(
        "mma.sync.aligned.m16n8k16.row.col.f32.bf16.bf16.f32 "
        "{%0,%1,%2,%3}, {%4,%5,%6,%7}, {%8,%9}, {%0,%1,%2,%3};"
        : "+f"(c[0]), "+f"(c[1]), "+f"(c[2]), "+f"(c[3])
        : "r"(a[0]), "r"(a[1]), "r"(a[2]), "r"(a[3]), "r"(b[0]), "r"(b[1]));
}
__device__ __forceinline__ void cpa16(uint32_t s, const void* g) {
    asm volatile("cp.async.cg.shared.global [%0], [%1], 16;" :: "r"(s), "l"(g));
}
__device__ __forceinline__ void cpa_commit() {
    asm volatile("cp.async.commit_group;" ::: "memory");
}
__device__ __forceinline__ void cpa_wait0() {
    asm volatile("cp.async.wait_group 0;" ::: "memory");
}
__device__ __forceinline__ void fsplit(float v, bf16& h, bf16& l) {
    h = __float2bfloat16(v);
    l = __float2bfloat16(v - __bfloat162float(h));
}

// ---------------- fused weight transpose + split (up to 4 weights) ----------
struct WSDesc { const float* W; bf16* H; bf16* L; int R, C, nz; };

__global__ void wsplit_multi(WSDesc d0, WSDesc d1, WSDesc d2, WSDesc d3,
                             int nb0, int nb1, int nb2, int nb3) {
    __shared__ float ts[32][33];
    int id = blockIdx.x;
    WSDesc d;
    if (id < nb0) { d = d0; }
    else if (id < nb0 + nb1) { d = d1; id -= nb0; }
    else if (id < nb0 + nb1 + nb2) { d = d2; id -= nb0 + nb1; }
    else { d = d3; id -= nb0 + nb1 + nb2; }
    int nbx = d.C >> 5, nby = d.R >> 5;
    int z = id / (nbx * nby);
    int rem = id - z * nbx * nby;
    int by = rem / nbx, bx = rem - by * nbx;
    size_t mo = (size_t)z * d.R * d.C;
    int c0 = bx * 32, r0 = by * 32;
    int tx = threadIdx.x, ty = threadIdx.y;
    #pragma unroll
    for (int i = 0; i < 4; ++i) {
        int r = r0 + ty + i * 8;
        ts[ty + i * 8][tx] = d.W[mo + (size_t)r * d.C + c0 + tx];
    }
    __syncthreads();
    #pragma unroll
    for (int i = 0; i < 4; ++i) {
        int n = c0 + ty + i * 8;
        int k = r0 + tx;
        float v = ts[tx][ty + i * 8];
        bf16 h = __float2bfloat16(v);
        d.H[mo + (size_t)n * d.R + k] = h;
        if (d.L)
            d.L[mo + (size_t)n * d.R + k] = __float2bfloat16(v - __bfloat162float(h));
    }
}

// ---------------- unified bf16 hi/lo tensor-core GEMM -----------------------
// OMODE 0: fp32 +bias/resid/relu | 1: scores | 3: bf16 linear | 5: fused QKV
// OMODE 6: LM-head fused logsumexp partials (no logits write)
// NPROD 3: ah*bh + ah*bl + al*bh | NPROD 1: ah*bh only
// KCAUS: truncate K to (blockIdx.x+1)*128 (attn·V)
struct QKVP {
    const bf16 *bh0, *bl0, *bh1, *bl1, *bh2, *bl2;
    bf16 *ch0, *cl0, *ch1, *cl1, *ch2, *cl2;
};

template<int BN, int OMODE, int NPROD, bool KCAUS>
__global__ __launch_bounds__(256, 2)
void gmma_kernel(const bf16* __restrict__ Ah, const bf16* __restrict__ Al,
                 const bf16* __restrict__ Bhp, const bf16* __restrict__ Blp,
                 float* __restrict__ C, bf16* __restrict__ Chp, bf16* __restrict__ Clp,
                 const float* __restrict__ bias, const float* __restrict__ resid,
                 int relu, int K, int lda, int ldb, int ldc,
                 size_t aZh, size_t aZl, size_t bZh, size_t bZl,
                 size_t cZh, size_t cZl, QKVP qp,
                 float* __restrict__ pm, float* __restrict__ ps,
                 float* __restrict__ tgtl, const int* __restrict__ tgts) {
    constexpr int STR = 80;
    constexpr int ALO = 128 * STR;
    constexpr int AROWS = (NPROD >= 3) ? 256 : 128;
    constexpr int BROWS = BN * ((NPROD == 3) ? 2 : 1);
    constexpr int BHO = AROWS * STR;
    constexpr int BLO = BHO + BN * STR;
    constexpr int SSZ = (AROWS + BROWS) * STR;
    constexpr int NT8 = BN / 32;
    constexpr int NB16 = NT8 / 2;
    constexpr int BSEG = BN * 4 / 256;
    extern __shared__ __align__(16) unsigned char smem[];

    int m0 = blockIdx.x * 128, n0 = blockIdx.y * BN;
    if (OMODE == 1 && n0 > m0) return;
    int z = blockIdx.z;
    const bf16 *Bh, *Bl = nullptr;
    bf16 *Ch = nullptr, *Cl = nullptr;
    if (OMODE == 5) {
        if (z == 0)      { Bh = qp.bh0; Bl = qp.bl0; Ch = qp.ch0; Cl = qp.cl0; }
        else if (z == 1) { Bh = qp.bh1; Bl = qp.bl1; Ch = qp.ch1; Cl = qp.cl1; }
        else             { Bh = qp.bh2; Bl = qp.bl2; Ch = qp.ch2; Cl = qp.cl2; }
    } else {
        Ah += (size_t)(z >> 4) * aZh + (size_t)(z & 15) * aZl;
        Al += (size_t)(z >> 4) * aZh + (size_t)(z & 15) * aZl;
        Bh = Bhp + (size_t)(z >> 4) * bZh + (size_t)(z & 15) * bZl;
        if (NPROD == 3) Bl = Blp + (size_t)(z >> 4) * bZh + (size_t)(z & 15) * bZl;
        if (OMODE == 0 || OMODE == 1)
            C += (size_t)(z >> 4) * cZh + (size_t)(z & 15) * cZl;
        else if (OMODE == 3) {
            Ch = Chp + (size_t)(z >> 4) * cZh + (size_t)(z & 15) * cZl;
            Cl = Clp + (size_t)(z >> 4) * cZh + (size_t)(z & 15) * cZl;
        }
    }

    int tid = threadIdx.x, lane = tid & 31, wid = tid >> 5;
    int wm = (wid & 1) * 64;
    int wn = (wid >> 1) * (BN / 4);

    float acc[4][NT8][4];
    #pragma unroll
    for (int i = 0; i < 4; ++i)
        #pragma unroll
        for (int j = 0; j < NT8; ++j)
            #pragma unroll
            for (int q = 0; q < 4; ++q) acc[i][j][q] = 0.f;

    uint32_t sbase = smem_u32(smem);
    int NC = KCAUS ? (blockIdx.x + 1) * 4 : (K / 32);

    auto load_stage = [&](int c) {
        uint32_t stg = sbase + (uint32_t)(c & 1) * SSZ;
        int kc = c * 32;
        #pragma unroll
        for (int i = 0; i < 2; ++i) {
            int slot = i * 256 + tid, r = slot >> 2, sg = slot & 3;
            uint32_t so = r * STR + sg * 16;
            size_t go = (size_t)(m0 + r) * lda + kc + sg * 8;
            cpa16(stg + so, Ah + go);
            if (NPROD >= 3) cpa16(stg + ALO + so, Al + go);
        }
        #pragma unroll
        for (int i = 0; i < BSEG; ++i) {
            int slot = i * 256 + tid, r = slot >> 2, sg = slot & 3;
            uint32_t so = r * STR + sg * 16;
            size_t go = (size_t)(n0 + r) * ldb + kc + sg * 8;
            cpa16(stg + BHO + so, Bh + go);
            if (NPROD == 3) cpa16(stg + BLO + so, Bl + go);
        }
        cpa_commit();
    };

    load_stage(0);
    uint32_t aAddr0 = sbase + (uint32_t)(wm + (lane & 15)) * STR + (lane >> 4) * 16;
    uint32_t bAddr0 = sbase + BHO + (uint32_t)(wn + (lane & 15)) * STR + (lane >> 4) * 16;

    for (int c = 0; c < NC; ++c) {
        cpa_wait0();
        __syncthreads();
        if (c + 1 < NC) load_stage(c + 1);
        uint32_t stg = (uint32_t)(c & 1) * SSZ;
        uint32_t aAddr = aAddr0 + stg, bAddr = bAddr0 + stg;
        #pragma unroll
        for (int ks = 0; ks < 2; ++ks) {
            uint32_t a[4][4];
            uint32_t bh[NT8][2], bl[NT8][2];
            #pragma unroll
            for (int g = 0; g < NB16; ++g) {
                uint32_t base = bAddr + g * 16 * STR + ks * 32;
                uint32_t r0, r1, r2, r3;
                ldsm4(r0, r1, r2, r3, base);
                bh[2*g][0] = r0; bh[2*g][1] = r2;
                bh[2*g+1][0] = r1; bh[2*g+1][1] = r3;
                if (NPROD == 3) {
                    ldsm4(r0, r1, r2, r3, base + BN * STR);
                    bl[2*g][0] = r0; bl[2*g][1] = r2;
                    bl[2*g+1][0] = r1; bl[2*g+1][1] = r3;
                }
            }
            #pragma unroll
            for (int mt = 0; mt < 4; ++mt) {
                uint32_t base = aAddr + mt * 16 * STR + ks * 32;
                ldsm4(a[mt][0], a[mt][1], a[mt][2], a[mt][3], base);
            }
            #pragma unroll
            for (int mt = 0; mt < 4; ++mt)
                #pragma unroll
                for (int n8 = 0; n8 < NT8; ++n8) {
                    mma16816(acc[mt][n8], a[mt], bh[n8]);
                    if (NPROD == 3) mma16816(acc[mt][n8], a[mt], bl[n8]);
                }
            if (NPROD >= 3) {
                #pragma unroll
                for (int mt = 0; mt < 4; ++mt) {
                    uint32_t base = aAddr + ALO + mt * 16 * STR + ks * 32;
                    ldsm4(a[mt][0], a[mt][1], a[mt][2], a[mt][3], base);
                }
                #pragma unroll
                for (int mt = 0; mt < 4; ++mt)
                    #pragma unroll
                    for (int n8 = 0; n8 < NT8; ++n8)
                        mma16816(acc[mt][n8], a[mt], bh[n8]);
            }
        }
    }

    int gid = lane >> 2, tig = lane & 3;

    if (OMODE == 6) {
        // fused per-tile logsumexp partials: pm/ps[(tileY, m)] + target logit
        __syncthreads();
        float* red  = (float*)smem;          // [128][4]
        float* red2 = red + 512;             // [128][4]
        int tileY = blockIdx.y;
        int wnw = wid >> 1;
        // pass 1: bias, per-row max, target capture
        #pragma unroll
        for (int mt = 0; mt < 4; ++mt)
            #pragma unroll
            for (int h2 = 0; h2 < 2; ++h2) {
                int m = m0 + wm + mt * 16 + gid + h2 * 8;
                int rloc = (wid & 1) * 64 + mt * 16 + gid + h2 * 8;
                int tg = tgts[m];
                float vmax = -3.4e38f;
                #pragma unroll
                for (int n8 = 0; n8 < NT8; ++n8)
                    #pragma unroll
                    for (int cc = 0; cc < 2; ++cc) {
                        int n = n0 + wn + n8 * 8 + tig * 2 + cc;
                        float v = acc[mt][n8][h2 * 2 + cc] + bias[n];
                        acc[mt][n8][h2 * 2 + cc] = v;
                        vmax = fmaxf(vmax, v);
                        if (n == tg) tgtl[m] = v;
                    }
                vmax = fmaxf(vmax, __shfl_xor_sync(~0u, vmax, 1));
                vmax = fmaxf(vmax, __shfl_xor_sync(~0u, vmax, 2));
                if (tig == 0) red[rloc * 4 + wnw] = vmax;
            }
        __syncthreads();
        // pass 2: per-row sumexp
        #pragma unroll
        for (int mt = 0; mt < 4; ++mt)
            #pragma unroll
            for (int h2 = 0; h2 < 2; ++h2) {
                int rloc = (wid & 1) * 64 + mt * 16 + gid + h2 * 8;
                float rm = fmaxf(fmaxf(red[rloc*4], red[rloc*4+1]),
                                 fmaxf(red[rloc*4+2], red[rloc*4+3]));
                float s = 0.f;
                #pragma unroll
                for (int n8 = 0; n8 < NT8; ++n8)
                    #pragma unroll
                    for (int cc = 0; cc < 2; ++cc)
                        s += __expf(acc[mt][n8][h2 * 2 + cc] - rm);
                s += __shfl_xor_sync(~0u, s, 1);
                s += __shfl_xor_sync(~0u, s, 2);
                if (tig == 0) red2[rloc * 4 + wnw] = s;
            }
        __syncthreads();
        // pass 3: one writer per row
        if (tig == 0 && wnw == 0) {
            #pragma unroll
            for (int mt = 0; mt < 4; ++mt)
                #pragma unroll
                for (int h2 = 0; h2 < 2; ++h2) {
                    int m = m0 + wm + mt * 16 + gid + h2 * 8;
                    int rloc = (wid & 1) * 64 + mt * 16 + gid + h2 * 8;
                    float rm = fmaxf(fmaxf(red[rloc*4], red[rloc*4+1]),
                                     fmaxf(red[rloc*4+2], red[rloc*4+3]));
                    pm[(size_t)tileY * BT + m] = rm;
                    ps[(size_t)tileY * BT + m] = red2[rloc*4] + red2[rloc*4+1] +
                                                 red2[rloc*4+2] + red2[rloc*4+3];
                }
        }
        return;
    }

    #pragma unroll
    for (int mt = 0; mt < 4; ++mt) {
        #pragma unroll
        for (int n8 = 0; n8 < NT8; ++n8) {
            int colb = n0 + wn + n8 * 8 + tig * 2;
            #pragma unroll
            for (int h2 = 0; h2 < 2; ++h2) {
                int m = m0 + wm + mt * 16 + gid + h2 * 8;
                #pragma unroll
                for (int cc = 0; cc < 2; ++cc) {
                    int n = colb + cc;
                    float v = acc[mt][n8][h2 * 2 + cc];
                    if (OMODE == 0) {
                        if (bias) v += bias[n];
                        if (resid) v += resid[(size_t)m * ldc + n];
                        if (relu) v = fmaxf(v, 0.f);
                        C[(size_t)m * ldc + n] = v;
                    } else if (OMODE == 1) {
                        C[(size_t)m * ldc + n] = v * 0.125f;
                    } else if (OMODE == 3) {
                        if (bias) v += bias[n];
                        if (relu) v = fmaxf(v, 0.f);
                        bf16 h, l; fsplit(v, h, l);
                        Ch[(size_t)m * ldc + n] = h;
                        Cl[(size_t)m * ldc + n] = l;
                    } else {  // OMODE 5
                        int b = m >> 10, t = m & 1023;
                        bf16 h, l; fsplit(v, h, l);
                        if (z < 2) {
                            size_t o = (size_t)(((b * 16 + (n >> 6)) << 10) + t) * 64 + (n & 63);
                            Ch[o] = h; Cl[o] = l;
                        } else {
                            size_t o = ((size_t)((b * 16 + (n >> 6)) * 64 + (n & 63)) << 10) + t;
                            Ch[o] = h; Cl[o] = l;
                        }
                    }
                }
            }
        }
    }
}

__global__ void embed_kernel(const int* __restrict__ idx,
                             const float* __restrict__ tok,
                             const float* __restrict__ pos) {
    size_t i = (size_t)blockIdx.x * 256 + threadIdx.x;
    int d  = (int)(i & (Dd - 1));
    int bt = (int)(i >> 10);
    int t  = bt & (Tt - 1);
    g_x[i] = tok[(size_t)idx[bt] * Dd + d] + pos[(size_t)t * Dd + d];
}

__global__ void ln_kernel(const float* __restrict__ x,
                          const float* __restrict__ g,
                          const float* __restrict__ b,
                          bf16* __restrict__ oh, bf16* __restrict__ ol) {
    __shared__ float s1[8], s2[8];
    int row = blockIdx.x;
    int tid = threadIdx.x, lane = tid & 31, wrp = tid >> 5;
    const float4* xr = (const float4*)(x + (size_t)row * Dd);
    float4 v = xr[tid];
    float a  = v.x + v.y + v.z + v.w;
    float a2 = v.x*v.x + v.y*v.y + v.z*v.z + v.w*v.w;
    #pragma unroll
    for (int o = 16; o > 0; o >>= 1) {
        a  += __shfl_xor_sync(~0u, a, o);
        a2 += __shfl_xor_sync(~0u, a2, o);
    }
    if (lane == 0) { s1[wrp] = a; s2[wrp] = a2; }
    __syncthreads();
    a = 0.f; a2 = 0.f;
    #pragma unroll
    for (int w = 0; w < 8; ++w) { a += s1[w]; a2 += s2[w]; }
    float mean = a * (1.f / Dd);
    float var  = a2 * (1.f / Dd) - mean * mean;
    float rstd = rsqrtf(var + EPSf);
    float4 gv = ((const float4*)g)[tid];
    float4 bv = ((const float4*)b)[tid];
    float r0 = (v.x - mean) * rstd * gv.x + bv.x;
    float r1 = (v.y - mean) * rstd * gv.y + bv.y;
    float r2 = (v.z - mean) * rstd * gv.z + bv.z;
    float r3 = (v.w - mean) * rstd * gv.w + bv.w;
    bf16 h0,l0,h1,l1,h2,l2,h3,l3;
    fsplit(r0,h0,l0); fsplit(r1,h1,l1); fsplit(r2,h2,l2); fsplit(r3,h3,l3);
    __nv_bfloat162 hv0{h0,h1}, hv1{h2,h3}, lv0{l0,l1}, lv1{l2,l3};
    uint2 hp, lp;
    hp.x = *(uint32_t*)&hv0; hp.y = *(uint32_t*)&hv1;
    lp.x = *(uint32_t*)&lv0; lp.y = *(uint32_t*)&lv1;
    ((uint2*)(oh + (size_t)row * Dd))[tid] = hp;
    ((uint2*)(ol + (size_t)row * Dd))[tid] = lp;
}

__global__ void softmax_kernel(float* __restrict__ attnL,
                               bf16* __restrict__ WH, bf16* __restrict__ WL) {
    __shared__ float sm[8];
    int rgl = blockIdx.x;
    int bh = rgl >> 10, t = rgl & (Tt - 1);
    size_t off = ((size_t)bh << 20) + ((size_t)t << 10);
    float* p = attnL + off;
    bf16* wh = WH + off;
    bf16* wl = WL + off;
    int tid = threadIdx.x, lane = tid & 31, wrp = tid >> 5;
    float v[4];
    float mx = -3.4e38f;
    #pragma unroll
    for (int k = 0; k < 4; ++k) {
        int i = k * 256 + tid;
        float x = p[i];
        v[k] = (i <= t) ? x : -3.4e38f;
        mx = fmaxf(mx, v[k]);
    }
    #pragma unroll
    for (int o = 16; o > 0; o >>= 1) mx = fmaxf(mx, __shfl_xor_sync(~0u, mx, o));
    if (lane == 0) sm[wrp] = mx;
    __syncthreads();
    mx = sm[0];
    #pragma unroll
    for (int w = 1; w < 8; ++w) mx = fmaxf(mx, sm[w]);
    float e[4], s = 0.f;
    #pragma unroll
    for (int k = 0; k < 4; ++k) {
        int i = k * 256 + tid;
        e[k] = (i <= t) ? __expf(v[k] - mx) : 0.f;
        s += e[k];
    }
    #pragma unroll
    for (int o = 16; o > 0; o >>= 1) s += __shfl_xor_sync(~0u, s, o);
    __syncthreads();
    if (lane == 0) sm[wrp] = s;
    __syncthreads();
    s = 0.f;
    #pragma unroll
    for (int w = 0; w < 8; ++w) s += sm[w];
    float inv = 1.f / s;
    #pragma unroll
    for (int k = 0; k < 4; ++k) {
        int i = k * 256 + tid;
        float r = e[k] * inv;
        p[i] = r;
        bf16 h, l; fsplit(r, h, l);
        wh[i] = h; wl[i] = l;
    }
}

// merge per-tile logsumexp partials (fixed order => deterministic)
__global__ void loss_lse_kernel() {
    int r = blockIdx.x * 256 + threadIdx.x;
    float m = -3.4e38f;
    for (int t = 0; t < NTIL; ++t)
        m = fmaxf(m, g_pmax[(size_t)t * BT + r]);
    float s = 0.f;
    for (int t = 0; t < NTIL; ++t)
        s += g_psum[(size_t)t * BT + r] * __expf(g_pmax[(size_t)t * BT + r] - m);
    g_rownll[r] = logf(s) + m - g_tgt[r];
}

__global__ void loss_final_kernel(float* __restrict__ out) {
    __shared__ float sd[256];
    int tid = threadIdx.x;
    float s = 0.f;
    for (int i = tid; i < BT; i += 256) s += g_rownll[i];
    sd[tid] = s; __syncthreads();
    for (int st = 128; st > 0; st >>= 1) {
        if (tid < st) sd[tid] += sd[tid + st];
        __syncthreads();
    }
    if (tid == 0) out[0] = sd[0] * (1.f / BT);
}

#define SM128_3 (2 * ((256 + 256) * 80))   // 81920
#define SM64_3  (2 * ((256 + 128) * 80))   // 61440
#define SM128_1 (2 * ((128 + 128) * 80))   // 40960

extern "C" void kernel_launch(void* const* d_in, const int* in_sizes, int n_in,
                              void* d_out, int out_size) {
    (void)in_sizes; (void)n_in; (void)out_size;
    const int*   idx     = (const int*)d_in[0];
    const int*   targets = (const int*)d_in[1];
    const float* tok     = (const float*)d_in[2];
    const float* pos     = (const float*)d_in[3];
    const float* ln1_g   = (const float*)d_in[4];
    const float* ln1_b   = (const float*)d_in[5];
    const float* Wq      = (const float*)d_in[6];
    const float* Wk      = (const float*)d_in[7];
    const float* Wv      = (const float*)d_in[8];
    const float* Wp      = (const float*)d_in[9];
    const float* bp      = (const float*)d_in[10];
    const float* ln2_g   = (const float*)d_in[11];
    const float* ln2_b   = (const float*)d_in[12];
    const float* W1      = (const float*)d_in[13];
    const float* b1      = (const float*)d_in[14];
    const float* W2      = (const float*)d_in[15];
    const float* b2      = (const float*)d_in[16];
    const float* lnf_g   = (const float*)d_in[17];
    const float* lnf_b   = (const float*)d_in[18];
    const float* Wlm     = (const float*)d_in[19];
    const float* blm     = (const float*)d_in[20];

    float* out  = (float*)d_out;
    float* attn = out + 1;

    cudaFuncSetAttribute(gmma_kernel<128, 0, 3, false>, cudaFuncAttributeMaxDynamicSharedMemorySize, SM128_3);
    cudaFuncSetAttribute(gmma_kernel<128, 1, 3, false>, cudaFuncAttributeMaxDynamicSharedMemorySize, SM128_3);
    cudaFuncSetAttribute(gmma_kernel<128, 3, 3, false>, cudaFuncAttributeMaxDynamicSharedMemorySize, SM128_3);
    cudaFuncSetAttribute(gmma_kernel<128, 5, 3, false>, cudaFuncAttributeMaxDynamicSharedMemorySize, SM128_3);
    cudaFuncSetAttribute(gmma_kernel<64,  3, 3, true >, cudaFuncAttributeMaxDynamicSharedMemorySize, SM64_3);
    cudaFuncSetAttribute(gmma_kernel<128, 6, 1, false>, cudaFuncAttributeMaxDynamicSharedMemorySize, SM128_1);

    float *px, *ppm, *pps, *ptg;
    cudaGetSymbolAddress((void**)&px,  g_x);
    cudaGetSymbolAddress((void**)&ppm, g_pmax);
    cudaGetSymbolAddress((void**)&pps, g_psum);
    cudaGetSymbolAddress((void**)&ptg, g_tgt);
    bf16 *hH,*hL,*qH,*qL,*kH,*kL,*vH,*vL,*oH,*oL,*fH,*fL,*wH,*wL;
    cudaGetSymbolAddress((void**)&hH, g_hH); cudaGetSymbolAddress((void**)&hL, g_hL);
    cudaGetSymbolAddress((void**)&qH, g_qH); cudaGetSymbolAddress((void**)&qL, g_qL);
    cudaGetSymbolAddress((void**)&kH, g_kH); cudaGetSymbolAddress((void**)&kL, g_kL);
    cudaGetSymbolAddress((void**)&vH, g_vH); cudaGetSymbolAddress((void**)&vL, g_vL);
    cudaGetSymbolAddress((void**)&oH, g_oH); cudaGetSymbolAddress((void**)&oL, g_oL);
    cudaGetSymbolAddress((void**)&fH, g_ffH); cudaGetSymbolAddress((void**)&fL, g_ffL);
    cudaGetSymbolAddress((void**)&wH, g_wH); cudaGetSymbolAddress((void**)&wL, g_wL);
    bf16 *wqh,*wql,*wkh,*wkl,*wvh,*wvl,*wph,*wpl,*w1h,*w1l,*w2h,*w2l,*wlh;
    cudaGetSymbolAddress((void**)&wqh, g_wqT_h); cudaGetSymbolAddress((void**)&wql, g_wqT_l);
    cudaGetSymbolAddress((void**)&wkh, g_wkT_h); cudaGetSymbolAddress((void**)&wkl, g_wkT_l);
    cudaGetSymbolAddress((void**)&wvh, g_wvT_h); cudaGetSymbolAddress((void**)&wvl, g_wvT_l);
    cudaGetSymbolAddress((void**)&wph, g_wpT_h); cudaGetSymbolAddress((void**)&wpl, g_wpT_l);
    cudaGetSymbolAddress((void**)&w1h, g_w1T_h); cudaGetSymbolAddress((void**)&w1l, g_w1T_l);
    cudaGetSymbolAddress((void**)&w2h, g_w2T_h); cudaGetSymbolAddress((void**)&w2l, g_w2T_l);
    cudaGetSymbolAddress((void**)&wlh, g_wlmT_h);

    {
        WSDesc a0{Wq, wqh, wql, Dd, HSs, Ll*Hh};
        WSDesc a1{Wk, wkh, wkl, Dd, HSs, Ll*Hh};
        WSDesc a2{Wv, wvh, wvl, Dd, HSs, Ll*Hh};
        WSDesc a3{Wp, wph, wpl, Dd, Dd,  Ll};
        int nb0 = (HSs/32)*(Dd/32)*Ll*Hh, nb3 = (Dd/32)*(Dd/32)*Ll;
        wsplit_multi<<<nb0*3 + nb3, dim3(32, 8)>>>(a0, a1, a2, a3, nb0, nb0, nb0, nb3);
        WSDesc b0{W1, w1h, w1l, Dd, FFf, Ll};
        WSDesc b1{W2, w2h, w2l, FFf, Dd, Ll};
        WSDesc b2{Wlm, wlh, nullptr, Dd, Vv, 1};
        WSDesc b3{Wlm, wlh, nullptr, Dd, Vv, 0};
        int m0n = (FFf/32)*(Dd/32)*Ll, m1n = (Dd/32)*(FFf/32)*Ll, m2n = (Vv/32)*(Dd/32);
        wsplit_multi<<<m0n + m1n + m2n, dim3(32, 8)>>>(b0, b1, b2, b3, m0n, m1n, m2n, 0);
    }

    embed_kernel<<<BT * Dd / 256, 256>>>(idx, tok, pos);

    QKVP qpz{};
    const size_t WQL = (size_t)Hh * HSs * Dd;
    for (int l = 0; l < Ll; ++l) {
        float* attnL = attn + (size_t)l * Bb * Hh * Tt * Tt;

        ln_kernel<<<BT, 256>>>(px, ln1_g + (size_t)l * Dd, ln1_b + (size_t)l * Dd, hH, hL);

        QKVP qp{wqh + l * WQL, wql + l * WQL,
                wkh + l * WQL, wkl + l * WQL,
                wvh + l * WQL, wvl + l * WQL,
                qH, qL, kH, kL, vH, vL};
        gmma_kernel<128, 5, 3, false><<<dim3(32, 8, 3), 256, SM128_3>>>(
            hH, hL, nullptr, nullptr, nullptr, nullptr, nullptr,
            nullptr, nullptr, 0, Dd, Dd, Dd, Dd, 0, 0, 0, 0, 0, 0, qp,
            nullptr, nullptr, nullptr, nullptr);

        gmma_kernel<128, 1, 3, false><<<dim3(8, 8, Bb * Hh), 256, SM128_3>>>(
            qH, qL, kH, kL, attnL, nullptr, nullptr, nullptr, nullptr, 0,
            HSs, HSs, HSs, Tt,
            (size_t)16 * Tt * HSs, (size_t)Tt * HSs,
            (size_t)16 * Tt * HSs, (size_t)Tt * HSs,
            (size_t)16 * Tt * Tt, (size_t)Tt * Tt, qpz,
            nullptr, nullptr, nullptr, nullptr);

        softmax_kernel<<<Bb * Hh * Tt, 256>>>(attnL, wH, wL);

        gmma_kernel<64, 3, 3, true><<<dim3(8, 1, Bb * Hh), 256, SM64_3>>>(
            wH, wL, vH, vL, nullptr, oH, oL, nullptr, nullptr, 0,
            Tt, Tt, Tt, Dd,
            (size_t)16 * Tt * Tt, (size_t)Tt * Tt,
            (size_t)16 * HSs * Tt, (size_t)HSs * Tt,
            (size_t)Tt * Dd, HSs, qpz,
            nullptr, nullptr, nullptr, nullptr);

        gmma_kernel<128, 0, 3, false><<<dim3(32, 8, 1), 256, SM128_3>>>(
            oH, oL, wph + (size_t)l * Dd * Dd, wpl + (size_t)l * Dd * Dd,
            px, nullptr, nullptr, bp + (size_t)l * Dd, px, 0,
            Dd, Dd, Dd, Dd, 0, 0, 0, 0, 0, 0, qpz,
            nullptr, nullptr, nullptr, nullptr);

        ln_kernel<<<BT, 256>>>(px, ln2_g + (size_t)l * Dd, ln2_b + (size_t)l * Dd, hH, hL);

        gmma_kernel<128, 3, 3, false><<<dim3(32, 32, 1), 256, SM128_3>>>(
            hH, hL, w1h + (size_t)l * Dd * FFf, w1l + (size_t)l * Dd * FFf,
            nullptr, fH, fL, b1 + (size_t)l * FFf, nullptr, 1,
            Dd, Dd, Dd, FFf, 0, 0, 0, 0, 0, 0, qpz,
            nullptr, nullptr, nullptr, nullptr);

        gmma_kernel<128, 0, 3, false><<<dim3(32, 8, 1), 256, SM128_3>>>(
            fH, fL, w2h + (size_t)l * FFf * Dd, w2l + (size_t)l * FFf * Dd,
            px, nullptr, nullptr, b2 + (size_t)l * Dd, px, 0,
            FFf, FFf, FFf, Dd, 0, 0, 0, 0, 0, 0, qpz,
            nullptr, nullptr, nullptr, nullptr);
    }

    ln_kernel<<<BT, 256>>>(px, lnf_g, lnf_b, hH, hL);

    // LM head: 1-product bf16, fused per-tile logsumexp — no logits buffer
    gmma_kernel<128, 6, 1, false><<<dim3(32, NTIL, 1), 256, SM128_1>>>(
        hH, hL, wlh, nullptr, nullptr, nullptr, nullptr, blm, nullptr, 0,
        Dd, Dd, Dd, Vv, 0, 0, 0, 0, 0, 0, qpz,
        ppm, pps, ptg, targets);

    loss_lse_kernel<<<BT / 256, 256>>>();
    loss_final_kernel<<<1, 256>>>(out);
}

// round 14
// speedup vs baseline: 1.1692x; 1.0771x over previous
#include <cuda_runtime.h>
#include <cuda_bf16.h>
#include <math.h>
#include <stdint.h>

#define Bb   4
#define Tt   1024
#define Dd   1024
#define Hh   16
#define HSs  64
#define Ll   4
#define FFf  4096
#define Vv   32000
#define BT   (Bb*Tt)
#define NTIL 250          // head N tiles (32000/128)
#define EPSf 1e-5f

typedef __nv_bfloat16 bf16;

__device__ float g_x[BT*Dd];
__device__ float g_rownll[BT];
__device__ float g_pmax[NTIL*BT], g_psum[NTIL*BT], g_tgt[BT];
__device__ __align__(16) bf16 g_hH[BT*Dd],  g_hL[BT*Dd];
__device__ __align__(16) bf16 g_qH[BT*Dd],  g_qL[BT*Dd];
__device__ __align__(16) bf16 g_kH[BT*Dd],  g_kL[BT*Dd];
__device__ __align__(16) bf16 g_vH[BT*Dd],  g_vL[BT*Dd];
__device__ __align__(16) bf16 g_oH[BT*Dd],  g_oL[BT*Dd];
__device__ __align__(16) bf16 g_ffH[(size_t)BT*FFf], g_ffL[(size_t)BT*FFf];
__device__ __align__(16) bf16 g_wH[(size_t)Bb*Hh*Tt*Tt], g_wL[(size_t)Bb*Hh*Tt*Tt];
__device__ __align__(16) bf16 g_wqT_h[Ll*Hh*HSs*Dd], g_wqT_l[Ll*Hh*HSs*Dd];
__device__ __align__(16) bf16 g_wkT_h[Ll*Hh*HSs*Dd], g_wkT_l[Ll*Hh*HSs*Dd];
__device__ __align__(16) bf16 g_wvT_h[Ll*Hh*HSs*Dd], g_wvT_l[Ll*Hh*HSs*Dd];
__device__ __align__(16) bf16 g_wpT_h[(size_t)Ll*Dd*Dd], g_wpT_l[(size_t)Ll*Dd*Dd];
__device__ __align__(16) bf16 g_w1T_h[(size_t)Ll*FFf*Dd], g_w1T_l[(size_t)Ll*FFf*Dd];
__device__ __align__(16) bf16 g_w2T_h[(size_t)Ll*Dd*FFf], g_w2T_l[(size_t)Ll*Dd*FFf];
__device__ __align__(16) bf16 g_wlmT_h[(size_t)Vv*Dd];

__device__ __forceinline__ uint32_t smem_u32(const void* p) {
    uint32_t a;
    asm("{ .reg .u64 t; cvta.to.shared.u64 t, %1; cvt.u32.u64 %0, t; }" : "=r"(a) : "l"(p));
    return a;
}
__device__ __forceinline__ void ldsm4(uint32_t& r0, uint32_t& r1, uint32_t& r2,
                                      uint32_t& r3, uint32_t addr) {
    asm volatile("ldmatrix.sync.aligned.m8n8.x4.shared.b16 {%0,%1,%2,%3}, [%4];"
                 : "=r"(r0), "=r"(r1), "=r"(r2), "=r"(r3) : "r"(addr));
}
__device__ __forceinline__ void mma16816(float* c, const uint32_t* a, const uint32_t* b) {
    asm volatile(
        "mma.sync.aligned.m16n8k16.row.col.f32.bf16.bf16.f32 "
        "{%0,%1,%2,%3}, {%4,%5,%6,%7}, {%8,%9}, {%0,%1,%2,%3};"
        : "+f"(c[0]), "+f"(c[1]), "+f"(c[2]), "+f"(c[3])
        : "r"(a[0]), "r"(a[1]), "r"(a[2]), "r"(a[3]), "r"(b[0]), "r"(b[1]));
}
__device__ __forceinline__ void cpa16(uint32_t s, const void* g) {
    asm volatile("cp.async.cg.shared.global [%0], [%1], 16;" :: "r"(s), "l"(g));
}
__device__ __forceinline__ void cpa_commit() {
    asm volatile("cp.async.commit_group;" ::: "memory");
}
__device__ __forceinline__ void cpa_wait0() {
    asm volatile("cp.async.wait_group 0;" ::: "memory");
}
__device__ __forceinline__ void fsplit(float v, bf16& h, bf16& l) {
    h = __float2bfloat16(v);
    l = __float2bfloat16(v - __bfloat162float(h));
}

// ---------------- fused weight transpose + split (up to 4 weights) ----------
struct WSDesc { const float* W; bf16* H; bf16* L; int R, C, nz; };

__global__ void wsplit_multi(WSDesc d0, WSDesc d1, WSDesc d2, WSDesc d3,
                             int nb0, int nb1, int nb2, int nb3) {
    __shared__ float ts[32][33];
    int id = blockIdx.x;
    WSDesc d;
    if (id < nb0) { d = d0; }
    else if (id < nb0 + nb1) { d = d1; id -= nb0; }
    else if (id < nb0 + nb1 + nb2) { d = d2; id -= nb0 + nb1; }
    else { d = d3; id -= nb0 + nb1 + nb2; }
    int nbx = d.C >> 5, nby = d.R >> 5;
    int z = id / (nbx * nby);
    int rem = id - z * nbx * nby;
    int by = rem / nbx, bx = rem - by * nbx;
    size_t mo = (size_t)z * d.R * d.C;
    int c0 = bx * 32, r0 = by * 32;
    int tx = threadIdx.x, ty = threadIdx.y;
    #pragma unroll
    for (int i = 0; i < 4; ++i) {
        int r = r0 + ty + i * 8;
        ts[ty + i * 8][tx] = d.W[mo + (size_t)r * d.C + c0 + tx];
    }
    __syncthreads();
    #pragma unroll
    for (int i = 0; i < 4; ++i) {
        int n = c0 + ty + i * 8;
        int k = r0 + tx;
        float v = ts[tx][ty + i * 8];
        bf16 h = __float2bfloat16(v);
        d.H[mo + (size_t)n * d.R + k] = h;
        if (d.L)
            d.L[mo + (size_t)n * d.R + k] = __float2bfloat16(v - __bfloat162float(h));
    }
}

// ---------------- unified bf16 hi/lo tensor-core GEMM -----------------------
// OMODE 0: fp32 +bias/resid/relu | 1: scores | 3: bf16 linear | 5: fused QKV
// OMODE 6: LM-head fused logsumexp partials (no logits write)
// NPROD 3: ah*bh + ah*bl + al*bh | NPROD 1: ah*bh only (pure bf16)
// KCAUS: truncate K to (blockIdx.x+1)*128 (attn·V)
struct QKVP {
    const bf16 *bh0, *bl0, *bh1, *bl1, *bh2, *bl2;
    bf16 *ch0, *cl0, *ch1, *cl1, *ch2, *cl2;
};

template<int BN, int OMODE, int NPROD, bool KCAUS>
__global__ __launch_bounds__(256, 2)
void gmma_kernel(const bf16* __restrict__ Ah, const bf16* __restrict__ Al,
                 const bf16* __restrict__ Bhp, const bf16* __restrict__ Blp,
                 float* __restrict__ C, bf16* __restrict__ Chp, bf16* __restrict__ Clp,
                 const float* __restrict__ bias, const float* __restrict__ resid,
                 int relu, int K, int lda, int ldb, int ldc,
                 size_t aZh, size_t aZl, size_t bZh, size_t bZl,
                 size_t cZh, size_t cZl, QKVP qp,
                 float* __restrict__ pm, float* __restrict__ ps,
                 float* __restrict__ tgtl, const int* __restrict__ tgts) {
    constexpr int STR = 80;
    constexpr int ALO = 128 * STR;
    constexpr int AROWS = (NPROD >= 3) ? 256 : 128;
    constexpr int BROWS = BN * ((NPROD == 3) ? 2 : 1);
    constexpr int BHO = AROWS * STR;
    constexpr int BLO = BHO + BN * STR;
    constexpr int SSZ = (AROWS + BROWS) * STR;
    constexpr int NT8 = BN / 32;
    constexpr int NB16 = NT8 / 2;
    constexpr int BSEG = BN * 4 / 256;
    extern __shared__ __align__(16) unsigned char smem[];

    int m0 = blockIdx.x * 128, n0 = blockIdx.y * BN;
    if (OMODE == 1 && n0 > m0) return;
    int z = blockIdx.z;
    const bf16 *Bh, *Bl = nullptr;
    bf16 *Ch = nullptr, *Cl = nullptr;
    if (OMODE == 5) {
        if (z == 0)      { Bh = qp.bh0; Bl = qp.bl0; Ch = qp.ch0; Cl = qp.cl0; }
        else if (z == 1) { Bh = qp.bh1; Bl = qp.bl1; Ch = qp.ch1; Cl = qp.cl1; }
        else             { Bh = qp.bh2; Bl = qp.bl2; Ch = qp.ch2; Cl = qp.cl2; }
    } else {
        Ah += (size_t)(z >> 4) * aZh + (size_t)(z & 15) * aZl;
        Al += (size_t)(z >> 4) * aZh + (size_t)(z & 15) * aZl;
        Bh = Bhp + (size_t)(z >> 4) * bZh + (size_t)(z & 15) * bZl;
        if (NPROD == 3) Bl = Blp + (size_t)(z >> 4) * bZh + (size_t)(z & 15) * bZl;
        if (OMODE == 0 || OMODE == 1)
            C += (size_t)(z >> 4) * cZh + (size_t)(z & 15) * cZl;
        else if (OMODE == 3) {
            Ch = Chp + (size_t)(z >> 4) * cZh + (size_t)(z & 15) * cZl;
            Cl = Clp + (size_t)(z >> 4) * cZh + (size_t)(z & 15) * cZl;
        }
    }

    int tid = threadIdx.x, lane = tid & 31, wid = tid >> 5;
    int wm = (wid & 1) * 64;
    int wn = (wid >> 1) * (BN / 4);

    float acc[4][NT8][4];
    #pragma unroll
    for (int i = 0; i < 4; ++i)
        #pragma unroll
        for (int j = 0; j < NT8; ++j)
            #pragma unroll
            for (int q = 0; q < 4; ++q) acc[i][j][q] = 0.f;

    uint32_t sbase = smem_u32(smem);
    int NC = KCAUS ? (blockIdx.x + 1) * 4 : (K / 32);

    auto load_stage = [&](int c) {
        uint32_t stg = sbase + (uint32_t)(c & 1) * SSZ;
        int kc = c * 32;
        #pragma unroll
        for (int i = 0; i < 2; ++i) {
            int slot = i * 256 + tid, r = slot >> 2, sg = slot & 3;
            uint32_t so = r * STR + sg * 16;
            size_t go = (size_t)(m0 + r) * lda + kc + sg * 8;
            cpa16(stg + so, Ah + go);
            if (NPROD >= 3) cpa16(stg + ALO + so, Al + go);
        }
        #pragma unroll
        for (int i = 0; i < BSEG; ++i) {
            int slot = i * 256 + tid, r = slot >> 2, sg = slot & 3;
            uint32_t so = r * STR + sg * 16;
            size_t go = (size_t)(n0 + r) * ldb + kc + sg * 8;
            cpa16(stg + BHO + so, Bh + go);
            if (NPROD == 3) cpa16(stg + BLO + so, Bl + go);
        }
        cpa_commit();
    };

    load_stage(0);
    uint32_t aAddr0 = sbase + (uint32_t)(wm + (lane & 15)) * STR + (lane >> 4) * 16;
    uint32_t bAddr0 = sbase + BHO + (uint32_t)(wn + (lane & 15)) * STR + (lane >> 4) * 16;

    for (int c = 0; c < NC; ++c) {
        cpa_wait0();
        __syncthreads();
        if (c + 1 < NC) load_stage(c + 1);
        uint32_t stg = (uint32_t)(c & 1) * SSZ;
        uint32_t aAddr = aAddr0 + stg, bAddr = bAddr0 + stg;
        #pragma unroll
        for (int ks = 0; ks < 2; ++ks) {
            uint32_t a[4][4];
            uint32_t bh[NT8][2], bl[NT8][2];
            #pragma unroll
            for (int g = 0; g < NB16; ++g) {
                uint32_t base = bAddr + g * 16 * STR + ks * 32;
                uint32_t r0, r1, r2, r3;
                ldsm4(r0, r1, r2, r3, base);
                bh[2*g][0] = r0; bh[2*g][1] = r2;
                bh[2*g+1][0] = r1; bh[2*g+1][1] = r3;
                if (NPROD == 3) {
                    ldsm4(r0, r1, r2, r3, base + BN * STR);
                    bl[2*g][0] = r0; bl[2*g][1] = r2;
                    bl[2*g+1][0] = r1; bl[2*g+1][1] = r3;
                }
            }
            #pragma unroll
            for (int mt = 0; mt < 4; ++mt) {
                uint32_t base = aAddr + mt * 16 * STR + ks * 32;
                ldsm4(a[mt][0], a[mt][1], a[mt][2], a[mt][3], base);
            }
            #pragma unroll
            for (int mt = 0; mt < 4; ++mt)
                #pragma unroll
                for (int n8 = 0; n8 < NT8; ++n8) {
                    mma16816(acc[mt][n8], a[mt], bh[n8]);
                    if (NPROD == 3) mma16816(acc[mt][n8], a[mt], bl[n8]);
                }
            if (NPROD >= 3) {
                #pragma unroll
                for (int mt = 0; mt < 4; ++mt) {
                    uint32_t base = aAddr + ALO + mt * 16 * STR + ks * 32;
                    ldsm4(a[mt][0], a[mt][1], a[mt][2], a[mt][3], base);
                }
                #pragma unroll
                for (int mt = 0; mt < 4; ++mt)
                    #pragma unroll
                    for (int n8 = 0; n8 < NT8; ++n8)
                        mma16816(acc[mt][n8], a[mt], bh[n8]);
            }
        }
    }

    int gid = lane >> 2, tig = lane & 3;

    if (OMODE == 6) {
        __syncthreads();
        float* red  = (float*)smem;
        float* red2 = red + 512;
        int tileY = blockIdx.y;
        int wnw = wid >> 1;
        #pragma unroll
        for (int mt = 0; mt < 4; ++mt)
            #pragma unroll
            for (int h2 = 0; h2 < 2; ++h2) {
                int m = m0 + wm + mt * 16 + gid + h2 * 8;
                int rloc = (wid & 1) * 64 + mt * 16 + gid + h2 * 8;
                int tg = tgts[m];
                float vmax = -3.4e38f;
                #pragma unroll
                for (int n8 = 0; n8 < NT8; ++n8)
                    #pragma unroll
                    for (int cc = 0; cc < 2; ++cc) {
                        int n = n0 + wn + n8 * 8 + tig * 2 + cc;
                        float v = acc[mt][n8][h2 * 2 + cc] + bias[n];
                        acc[mt][n8][h2 * 2 + cc] = v;
                        vmax = fmaxf(vmax, v);
                        if (n == tg) tgtl[m] = v;
                    }
                vmax = fmaxf(vmax, __shfl_xor_sync(~0u, vmax, 1));
                vmax = fmaxf(vmax, __shfl_xor_sync(~0u, vmax, 2));
                if (tig == 0) red[rloc * 4 + wnw] = vmax;
            }
        __syncthreads();
        #pragma unroll
        for (int mt = 0; mt < 4; ++mt)
            #pragma unroll
            for (int h2 = 0; h2 < 2; ++h2) {
                int rloc = (wid & 1) * 64 + mt * 16 + gid + h2 * 8;
                float rm = fmaxf(fmaxf(red[rloc*4], red[rloc*4+1]),
                                 fmaxf(red[rloc*4+2], red[rloc*4+3]));
                float s = 0.f;
                #pragma unroll
                for (int n8 = 0; n8 < NT8; ++n8)
                    #pragma unroll
                    for (int cc = 0; cc < 2; ++cc)
                        s += __expf(acc[mt][n8][h2 * 2 + cc] - rm);
                s += __shfl_xor_sync(~0u, s, 1);
                s += __shfl_xor_sync(~0u, s, 2);
                if (tig == 0) red2[rloc * 4 + wnw] = s;
            }
        __syncthreads();
        if (tig == 0 && wnw == 0) {
            #pragma unroll
            for (int mt = 0; mt < 4; ++mt)
                #pragma unroll
                for (int h2 = 0; h2 < 2; ++h2) {
                    int m = m0 + wm + mt * 16 + gid + h2 * 8;
                    int rloc = (wid & 1) * 64 + mt * 16 + gid + h2 * 8;
                    float rm = fmaxf(fmaxf(red[rloc*4], red[rloc*4+1]),
                                     fmaxf(red[rloc*4+2], red[rloc*4+3]));
                    pm[(size_t)tileY * BT + m] = rm;
                    ps[(size_t)tileY * BT + m] = red2[rloc*4] + red2[rloc*4+1] +
                                                 red2[rloc*4+2] + red2[rloc*4+3];
                }
        }
        return;
    }

    #pragma unroll
    for (int mt = 0; mt < 4; ++mt) {
        #pragma unroll
        for (int n8 = 0; n8 < NT8; ++n8) {
            int colb = n0 + wn + n8 * 8 + tig * 2;
            #pragma unroll
            for (int h2 = 0; h2 < 2; ++h2) {
                int m = m0 + wm + mt * 16 + gid + h2 * 8;
                #pragma unroll
                for (int cc = 0; cc < 2; ++cc) {
                    int n = colb + cc;
                    float v = acc[mt][n8][h2 * 2 + cc];
                    if (OMODE == 0) {
                        if (bias) v += bias[n];
                        if (resid) v += resid[(size_t)m * ldc + n];
                        if (relu) v = fmaxf(v, 0.f);
                        C[(size_t)m * ldc + n] = v;
                    } else if (OMODE == 1) {
                        C[(size_t)m * ldc + n] = v * 0.125f;
                    } else if (OMODE == 3) {
                        if (bias) v += bias[n];
                        if (relu) v = fmaxf(v, 0.f);
                        bf16 h, l; fsplit(v, h, l);
                        Ch[(size_t)m * ldc + n] = h;
                        Cl[(size_t)m * ldc + n] = l;
                    } else {  // OMODE 5
                        int b = m >> 10, t = m & 1023;
                        bf16 h, l; fsplit(v, h, l);
                        if (z < 2) {
                            size_t o = (size_t)(((b * 16 + (n >> 6)) << 10) + t) * 64 + (n & 63);
                            Ch[o] = h; Cl[o] = l;
                        } else {
                            size_t o = ((size_t)((b * 16 + (n >> 6)) * 64 + (n & 63)) << 10) + t;
                            Ch[o] = h; Cl[o] = l;
                        }
                    }
                }
            }
        }
    }
}

__global__ void embed_kernel(const int* __restrict__ idx,
                             const float* __restrict__ tok,
                             const float* __restrict__ pos) {
    size_t i = (size_t)blockIdx.x * 256 + threadIdx.x;
    int d  = (int)(i & (Dd - 1));
    int bt = (int)(i >> 10);
    int t  = bt & (Tt - 1);
    g_x[i] = tok[(size_t)idx[bt] * Dd + d] + pos[(size_t)t * Dd + d];
}

__global__ void ln_kernel(const float* __restrict__ x,
                          const float* __restrict__ g,
                          const float* __restrict__ b,
                          bf16* __restrict__ oh, bf16* __restrict__ ol) {
    __shared__ float s1[8], s2[8];
    int row = blockIdx.x;
    int tid = threadIdx.x, lane = tid & 31, wrp = tid >> 5;
    const float4* xr = (const float4*)(x + (size_t)row * Dd);
    float4 v = xr[tid];
    float a  = v.x + v.y + v.z + v.w;
    float a2 = v.x*v.x + v.y*v.y + v.z*v.z + v.w*v.w;
    #pragma unroll
    for (int o = 16; o > 0; o >>= 1) {
        a  += __shfl_xor_sync(~0u, a, o);
        a2 += __shfl_xor_sync(~0u, a2, o);
    }
    if (lane == 0) { s1[wrp] = a; s2[wrp] = a2; }
    __syncthreads();
    a = 0.f; a2 = 0.f;
    #pragma unroll
    for (int w = 0; w < 8; ++w) { a += s1[w]; a2 += s2[w]; }
    float mean = a * (1.f / Dd);
    float var  = a2 * (1.f / Dd) - mean * mean;
    float rstd = rsqrtf(var + EPSf);
    float4 gv = ((const float4*)g)[tid];
    float4 bv = ((const float4*)b)[tid];
    float r0 = (v.x - mean) * rstd * gv.x + bv.x;
    float r1 = (v.y - mean) * rstd * gv.y + bv.y;
    float r2 = (v.z - mean) * rstd * gv.z + bv.z;
    float r3 = (v.w - mean) * rstd * gv.w + bv.w;
    bf16 h0,l0,h1,l1,h2,l2,h3,l3;
    fsplit(r0,h0,l0); fsplit(r1,h1,l1); fsplit(r2,h2,l2); fsplit(r3,h3,l3);
    __nv_bfloat162 hv0{h0,h1}, hv1{h2,h3}, lv0{l0,l1}, lv1{l2,l3};
    uint2 hp, lp;
    hp.x = *(uint32_t*)&hv0; hp.y = *(uint32_t*)&hv1;
    lp.x = *(uint32_t*)&lv0; lp.y = *(uint32_t*)&lv1;
    ((uint2*)(oh + (size_t)row * Dd))[tid] = hp;
    ((uint2*)(ol + (size_t)row * Dd))[tid] = lp;
}

__global__ void softmax_kernel(float* __restrict__ attnL,
                               bf16* __restrict__ WH, bf16* __restrict__ WL) {
    __shared__ float sm[8];
    int rgl = blockIdx.x;
    int bh = rgl >> 10, t = rgl & (Tt - 1);
    size_t off = ((size_t)bh << 20) + ((size_t)t << 10);
    float* p = attnL + off;
    bf16* wh = WH + off;
    bf16* wl = WL + off;
    int tid = threadIdx.x, lane = tid & 31, wrp = tid >> 5;
    float v[4];
    float mx = -3.4e38f;
    #pragma unroll
    for (int k = 0; k < 4; ++k) {
        int i = k * 256 + tid;
        v[k] = (i <= t) ? p[i] : -3.4e38f;   // causal-conditional load
        mx = fmaxf(mx, v[k]);
    }
    #pragma unroll
    for (int o = 16; o > 0; o >>= 1) mx = fmaxf(mx, __shfl_xor_sync(~0u, mx, o));
    if (lane == 0) sm[wrp] = mx;
    __syncthreads();
    mx = sm[0];
    #pragma unroll
    for (int w = 1; w < 8; ++w) mx = fmaxf(mx, sm[w]);
    float e[4], s = 0.f;
    #pragma unroll
    for (int k = 0; k < 4; ++k) {
        int i = k * 256 + tid;
        e[k] = (i <= t) ? __expf(v[k] - mx) : 0.f;
        s += e[k];
    }
    #pragma unroll
    for (int o = 16; o > 0; o >>= 1) s += __shfl_xor_sync(~0u, s, o);
    __syncthreads();
    if (lane == 0) sm[wrp] = s;
    __syncthreads();
    s = 0.f;
    #pragma unroll
    for (int w = 0; w < 8; ++w) s += sm[w];
    float inv = 1.f / s;
    #pragma unroll
    for (int k = 0; k < 4; ++k) {
        int i = k * 256 + tid;
        float r = e[k] * inv;
        p[i] = r;
        bf16 h, l; fsplit(r, h, l);
        wh[i] = h; wl[i] = l;
    }
}

__global__ void loss_lse_kernel() {
    int r = blockIdx.x * 256 + threadIdx.x;
    float m = -3.4e38f;
    for (int t = 0; t < NTIL; ++t)
        m = fmaxf(m, g_pmax[(size_t)t * BT + r]);
    float s = 0.f;
    for (int t = 0; t < NTIL; ++t)
        s += g_psum[(size_t)t * BT + r] * __expf(g_pmax[(size_t)t * BT + r] - m);
    g_rownll[r] = logf(s) + m - g_tgt[r];
}

__global__ void loss_final_kernel(float* __restrict__ out) {
    __shared__ float sd[256];
    int tid = threadIdx.x;
    float s = 0.f;
    for (int i = tid; i < BT; i += 256) s += g_rownll[i];
    sd[tid] = s; __syncthreads();
    for (int st = 128; st > 0; st >>= 1) {
        if (tid < st) sd[tid] += sd[tid + st];
        __syncthreads();
    }
    if (tid == 0) out[0] = sd[0] * (1.f / BT);
}

#define SM128_3 (2 * ((256 + 256) * 80))   // 81920
#define SM64_3  (2 * ((256 + 128) * 80))   // 61440
#define SM128_1 (2 * ((128 + 128) * 80))   // 40960

extern "C" void kernel_launch(void* const* d_in, const int* in_sizes, int n_in,
                              void* d_out, int out_size) {
    (void)in_sizes; (void)n_in; (void)out_size;
    const int*   idx     = (const int*)d_in[0];
    const int*   targets = (const int*)d_in[1];
    const float* tok     = (const float*)d_in[2];
    const float* pos     = (const float*)d_in[3];
    const float* ln1_g   = (const float*)d_in[4];
    const float* ln1_b   = (const float*)d_in[5];
    const float* Wq      = (const float*)d_in[6];
    const float* Wk      = (const float*)d_in[7];
    const float* Wv      = (const float*)d_in[8];
    const float* Wp      = (const float*)d_in[9];
    const float* bp      = (const float*)d_in[10];
    const float* ln2_g   = (const float*)d_in[11];
    const float* ln2_b   = (const float*)d_in[12];
    const float* W1      = (const float*)d_in[13];
    const float* b1      = (const float*)d_in[14];
    const float* W2      = (const float*)d_in[15];
    const float* b2      = (const float*)d_in[16];
    const float* lnf_g   = (const float*)d_in[17];
    const float* lnf_b   = (const float*)d_in[18];
    const float* Wlm     = (const float*)d_in[19];
    const float* blm     = (const float*)d_in[20];

    float* out  = (float*)d_out;
    float* attn = out + 1;

    cudaFuncSetAttribute(gmma_kernel<128, 0, 3, false>, cudaFuncAttributeMaxDynamicSharedMemorySize, SM128_3);
    cudaFuncSetAttribute(gmma_kernel<128, 0, 1, false>, cudaFuncAttributeMaxDynamicSharedMemorySize, SM128_1);
    cudaFuncSetAttribute(gmma_kernel<128, 1, 3, false>, cudaFuncAttributeMaxDynamicSharedMemorySize, SM128_3);
    cudaFuncSetAttribute(gmma_kernel<128, 3, 3, false>, cudaFuncAttributeMaxDynamicSharedMemorySize, SM128_3);
    cudaFuncSetAttribute(gmma_kernel<128, 3, 1, false>, cudaFuncAttributeMaxDynamicSharedMemorySize, SM128_1);
    cudaFuncSetAttribute(gmma_kernel<128, 5, 3, false>, cudaFuncAttributeMaxDynamicSharedMemorySize, SM128_3);
    cudaFuncSetAttribute(gmma_kernel<64,  3, 3, true >, cudaFuncAttributeMaxDynamicSharedMemorySize, SM64_3);
    cudaFuncSetAttribute(gmma_kernel<128, 6, 1, false>, cudaFuncAttributeMaxDynamicSharedMemorySize, SM128_1);

    float *px, *ppm, *pps, *ptg;
    cudaGetSymbolAddress((void**)&px,  g_x);
    cudaGetSymbolAddress((void**)&ppm, g_pmax);
    cudaGetSymbolAddress((void**)&pps, g_psum);
    cudaGetSymbolAddress((void**)&ptg, g_tgt);
    bf16 *hH,*hL,*qH,*qL,*kH,*kL,*vH,*vL,*oH,*oL,*fH,*fL,*wH,*wL;
    cudaGetSymbolAddress((void**)&hH, g_hH); cudaGetSymbolAddress((void**)&hL, g_hL);
    cudaGetSymbolAddress((void**)&qH, g_qH); cudaGetSymbolAddress((void**)&qL, g_qL);
    cudaGetSymbolAddress((void**)&kH, g_kH); cudaGetSymbolAddress((void**)&kL, g_kL);
    cudaGetSymbolAddress((void**)&vH, g_vH); cudaGetSymbolAddress((void**)&vL, g_vL);
    cudaGetSymbolAddress((void**)&oH, g_oH); cudaGetSymbolAddress((void**)&oL, g_oL);
    cudaGetSymbolAddress((void**)&fH, g_ffH); cudaGetSymbolAddress((void**)&fL, g_ffL);
    cudaGetSymbolAddress((void**)&wH, g_wH); cudaGetSymbolAddress((void**)&wL, g_wL);
    bf16 *wqh,*wql,*wkh,*wkl,*wvh,*wvl,*wph,*wpl,*w1h,*w1l,*w2h,*w2l,*wlh;
    cudaGetSymbolAddress((void**)&wqh, g_wqT_h); cudaGetSymbolAddress((void**)&wql, g_wqT_l);
    cudaGetSymbolAddress((void**)&wkh, g_wkT_h); cudaGetSymbolAddress((void**)&wkl, g_wkT_l);
    cudaGetSymbolAddress((void**)&wvh, g_wvT_h); cudaGetSymbolAddress((void**)&wvl, g_wvT_l);
    cudaGetSymbolAddress((void**)&wph, g_wpT_h); cudaGetSymbolAddress((void**)&wpl, g_wpT_l);
    cudaGetSymbolAddress((void**)&w1h, g_w1T_h); cudaGetSymbolAddress((void**)&w1l, g_w1T_l);
    cudaGetSymbolAddress((void**)&w2h, g_w2T_h); cudaGetSymbolAddress((void**)&w2l, g_w2T_l);
    cudaGetSymbolAddress((void**)&wlh, g_wlmT_h);

    {
        WSDesc a0{Wq, wqh, wql, Dd, HSs, Ll*Hh};
        WSDesc a1{Wk, wkh, wkl, Dd, HSs, Ll*Hh};
        WSDesc a2{Wv, wvh, wvl, Dd, HSs, Ll*Hh};
        WSDesc a3{Wp, wph, wpl, Dd, Dd,  Ll};
        int nb0 = (HSs/32)*(Dd/32)*Ll*Hh, nb3 = (Dd/32)*(Dd/32)*Ll;
        wsplit_multi<<<nb0*3 + nb3, dim3(32, 8)>>>(a0, a1, a2, a3, nb0, nb0, nb0, nb3);
        WSDesc b0{W1, w1h, w1l, Dd, FFf, Ll};
        WSDesc b1{W2, w2h, w2l, FFf, Dd, Ll};
        WSDesc b2{Wlm, wlh, nullptr, Dd, Vv, 1};
        WSDesc b3{Wlm, wlh, nullptr, Dd, Vv, 0};
        int m0n = (FFf/32)*(Dd/32)*Ll, m1n = (Dd/32)*(FFf/32)*Ll, m2n = (Vv/32)*(Dd/32);
        wsplit_multi<<<m0n + m1n + m2n, dim3(32, 8)>>>(b0, b1, b2, b3, m0n, m1n, m2n, 0);
    }

    embed_kernel<<<BT * Dd / 256, 256>>>(idx, tok, pos);

    QKVP qpz{};
    const size_t WQL = (size_t)Hh * HSs * Dd;
    for (int l = 0; l < Ll; ++l) {
        float* attnL = attn + (size_t)l * Bb * Hh * Tt * Tt;
        bool last = (l == Ll - 1);   // post-attn GEMMs of last layer feed loss only

        ln_kernel<<<BT, 256>>>(px, ln1_g + (size_t)l * Dd, ln1_b + (size_t)l * Dd, hH, hL);

        QKVP qp{wqh + l * WQL, wql + l * WQL,
                wkh + l * WQL, wkl + l * WQL,
                wvh + l * WQL, wvl + l * WQL,
                qH, qL, kH, kL, vH, vL};
        gmma_kernel<128, 5, 3, false><<<dim3(32, 8, 3), 256, SM128_3>>>(
            hH, hL, nullptr, nullptr, nullptr, nullptr, nullptr,
            nullptr, nullptr, 0, Dd, Dd, Dd, Dd, 0, 0, 0, 0, 0, 0, qp,
            nullptr, nullptr, nullptr, nullptr);

        gmma_kernel<128, 1, 3, false><<<dim3(8, 8, Bb * Hh), 256, SM128_3>>>(
            qH, qL, kH, kL, attnL, nullptr, nullptr, nullptr, nullptr, 0,
            HSs, HSs, HSs, Tt,
            (size_t)16 * Tt * HSs, (size_t)Tt * HSs,
            (size_t)16 * Tt * HSs, (size_t)Tt * HSs,
            (size_t)16 * Tt * Tt, (size_t)Tt * Tt, qpz,
            nullptr, nullptr, nullptr, nullptr);

        softmax_kernel<<<Bb * Hh * Tt, 256>>>(attnL, wH, wL);

        gmma_kernel<64, 3, 3, true><<<dim3(8, 1, Bb * Hh), 256, SM64_3>>>(
            wH, wL, vH, vL, nullptr, oH, oL, nullptr, nullptr, 0,
            Tt, Tt, Tt, Dd,
            (size_t)16 * Tt * Tt, (size_t)Tt * Tt,
            (size_t)16 * HSs * Tt, (size_t)HSs * Tt,
            (size_t)Tt * Dd, HSs, qpz,
            nullptr, nullptr, nullptr, nullptr);

        if (!last) {
            gmma_kernel<128, 0, 3, false><<<dim3(32, 8, 1), 256, SM128_3>>>(
                oH, oL, wph + (size_t)l * Dd * Dd, wpl + (size_t)l * Dd * Dd,
                px, nullptr, nullptr, bp + (size_t)l * Dd, px, 0,
                Dd, Dd, Dd, Dd, 0, 0, 0, 0, 0, 0, qpz,
                nullptr, nullptr, nullptr, nullptr);
        } else {
            gmma_kernel<128, 0, 1, false><<<dim3(32, 8, 1), 256, SM128_1>>>(
                oH, oL, wph + (size_t)l * Dd * Dd, nullptr,
                px, nullptr, nullptr, bp + (size_t)l * Dd, px, 0,
                Dd, Dd, Dd, Dd, 0, 0, 0, 0, 0, 0, qpz,
                nullptr, nullptr, nullptr, nullptr);
        }

        ln_kernel<<<BT, 256>>>(px, ln2_g + (size_t)l * Dd, ln2_b + (size_t)l * Dd, hH, hL);

        if (!last) {
            gmma_kernel<128, 3, 3, false><<<dim3(32, 32, 1), 256, SM128_3>>>(
                hH, hL, w1h + (size_t)l * Dd * FFf, w1l + (size_t)l * Dd * FFf,
                nullptr, fH, fL, b1 + (size_t)l * FFf, nullptr, 1,
                Dd, Dd, Dd, FFf, 0, 0, 0, 0, 0, 0, qpz,
                nullptr, nullptr, nullptr, nullptr);
            gmma_kernel<128, 0, 3, false><<<dim3(32, 8, 1), 256, SM128_3>>>(
                fH, fL, w2h + (size_t)l * FFf * Dd, w2l + (size_t)l * FFf * Dd,
                px, nullptr, nullptr, b2 + (size_t)l * Dd, px, 0,
                FFf, FFf, FFf, Dd, 0, 0, 0, 0, 0, 0, qpz,
                nullptr, nullptr, nullptr, nullptr);
        } else {
            gmma_kernel<128, 3, 1, false><<<dim3(32, 32, 1), 256, SM128_1>>>(
                hH, hL, w1h + (size_t)l * Dd * FFf, nullptr,
                nullptr, fH, fL, b1 + (size_t)l * FFf, nullptr, 1,
                Dd, Dd, Dd, FFf, 0, 0, 0, 0, 0, 0, qpz,
                nullptr, nullptr, nullptr, nullptr);
            gmma_kernel<128, 0, 1, false><<<dim3(32, 8, 1), 256, SM128_1>>>(
                fH, fL, w2h + (size_t)l * FFf * Dd, nullptr,
                px, nullptr, nullptr, b2 + (size_t)l * Dd, px, 0,
                FFf, FFf, FFf, Dd, 0, 0, 0, 0, 0, 0, qpz,
                nullptr, nullptr, nullptr, nullptr);
        }
    }

    ln_kernel<<<BT, 256>>>(px, lnf_g, lnf_b, hH, hL);

    // LM head: 1-product bf16, fused per-tile logsumexp — no logits buffer
    gmma_kernel<128, 6, 1, false><<<dim3(32, NTIL, 1), 256, SM128_1>>>(
        hH, hL, wlh, nullptr, nullptr, nullptr, nullptr, blm, nullptr, 0,
        Dd, Dd, Dd, Vv, 0, 0, 0, 0, 0, 0, qpz,
        ppm, pps, ptg, targets);

    loss_lse_kernel<<<BT / 256, 256>>>();
    loss_final_kernel<<<1, 256>>>(out);
}